// round 8
// baseline (speedup 1.0000x reference)
#include <cuda_runtime.h>
#include <cuda_bf16.h>
#include <cstdint>
#include <math.h>

// Problem constants
#define BATCH 4096
#define D_IN  1024
#define DF    256
#define NM    10
#define NK    8
#define NMK   80
#define LOG2PI_F 1.8378770664093453f

// ---------------- scratch (no cudaMalloc allowed) ----------------
__device__ __align__(16) float          g_Ainv[NMK * DF * DF]; // fp32 L^-1 (upper zeroed)
__device__ __align__(16) __nv_bfloat16  g_xhi[BATCH * D_IN];   // x hi, [b][k]
__device__ __align__(16) __nv_bfloat16  g_xlo[BATCH * D_IN];   // x lo
__device__ __align__(16) __nv_bfloat16  g_Whi[DF * D_IN];      // W^T hi, [n][k]
__device__ __align__(16) __nv_bfloat16  g_Wlo[DF * D_IN];      // W^T lo
__device__ __align__(16) __nv_bfloat16  g_fhi[BATCH * DF];     // feats hi, [b][d]
__device__ __align__(16) __nv_bfloat16  g_flo[BATCH * DF];     // feats lo
__device__ __align__(16) __nv_bfloat16  g_Bhi[NMK * DF * DF];  // Ainv hi, [mk][d][k]
__device__ __align__(16) __nv_bfloat16  g_Blo[NMK * DF * DF];  // Ainv lo
__device__ float g_v[NMK * DF];                                 // Ainv @ mean (fp32)
__device__ float g_c1[NMK];                                     // -0.5 * w
__device__ float g_c2[NMK];                                     // w*(-0.5*DF*log2pi) - w*logdet

// chunk schedule for k_quad_mma (10 chunks: dblk-major, kc inner)
__constant__ int c_CD[10] = {0, 1, 1, 2, 2, 2, 3, 3, 3, 3};
__constant__ int c_CK[10] = {0, 0, 1, 0, 1, 2, 0, 1, 2, 3};

// ---------------- helpers ----------------
__device__ __forceinline__ uint32_t smem_u32(const void* p) {
    uint32_t a;
    asm("{ .reg .u64 t; cvta.to.shared.u64 t, %1; cvt.u32.u64 %0, t; }" : "=r"(a) : "l"(p));
    return a;
}

#define LDSM4(r, addr) \
    asm volatile("ldmatrix.sync.aligned.m8n8.x4.shared.b16 {%0,%1,%2,%3}, [%4];" \
        : "=r"((r)[0]), "=r"((r)[1]), "=r"((r)[2]), "=r"((r)[3]) : "r"(addr))

#define MMA16816(d, a, b) \
    asm volatile("mma.sync.aligned.m16n8k16.row.col.f32.bf16.bf16.f32 " \
        "{%0,%1,%2,%3},{%4,%5,%6,%7},{%8,%9},{%0,%1,%2,%3};" \
        : "+f"((d)[0]), "+f"((d)[1]), "+f"((d)[2]), "+f"((d)[3]) \
        : "r"((a)[0]), "r"((a)[1]), "r"((a)[2]), "r"((a)[3]), "r"((b)[0]), "r"((b)[1]))

#define CP16(saddr, gptr) \
    asm volatile("cp.async.cg.shared.global [%0], [%1], 16;" :: "r"(saddr), "l"(gptr) : "memory")
#define CP_COMMIT() asm volatile("cp.async.commit_group;" ::: "memory")
#define CP_WAIT1()  asm volatile("cp.async.wait_group 1;" ::: "memory")
#define CP_WAIT0()  asm volatile("cp.async.wait_group 0;" ::: "memory")

// feats stage buffer (48 KB per stage)
#define STG_SZ   49152
#define STG_FHI  0
#define STG_FLO  16384
#define STG_AHI  32768
#define STG_ALO  40960

// quad stage buffer (80 KB per stage): F 256x64 hi/lo, A 64x64 hi/lo
#define STG2_SZ  81920
#define ST2_FHI  0
#define ST2_FLO  32768
#define ST2_AHI  65536
#define ST2_ALO  73728
#define OFQ2_V   163840
#define OFQ2_Q   164864
#define QUAD2_SMEM 166912

// ---------------------------------------------------------------------------
// split kernels
// ---------------------------------------------------------------------------
__global__ __launch_bounds__(256) void k_xsplit(const float* __restrict__ x)
{
    size_t idx = ((size_t)blockIdx.x * 256 + threadIdx.x) * 4;
    float4 v = *(const float4*)&x[idx];
    __nv_bfloat162 h01, h23, l01, l23;
    h01.x = __float2bfloat16(v.x);  l01.x = __float2bfloat16(v.x - __bfloat162float(h01.x));
    h01.y = __float2bfloat16(v.y);  l01.y = __float2bfloat16(v.y - __bfloat162float(h01.y));
    h23.x = __float2bfloat16(v.z);  l23.x = __float2bfloat16(v.z - __bfloat162float(h23.x));
    h23.y = __float2bfloat16(v.w);  l23.y = __float2bfloat16(v.w - __bfloat162float(h23.y));
    *(__nv_bfloat162*)&g_xhi[idx]     = h01;
    *(__nv_bfloat162*)&g_xhi[idx + 2] = h23;
    *(__nv_bfloat162*)&g_xlo[idx]     = l01;
    *(__nv_bfloat162*)&g_xlo[idx + 2] = l23;
}

// W [k][n] fp32 -> W^T [n][k] bf16 hi/lo via smem 32x32 transpose
__global__ __launch_bounds__(256) void k_wsplit(const float* __restrict__ W)
{
    __shared__ float t[32][33];
    const int k0 = blockIdx.x * 32;
    const int n0 = blockIdx.y * 32;
    const int tx = threadIdx.x & 31, ty = threadIdx.x >> 5;
#pragma unroll
    for (int i = 0; i < 4; i++)
        t[ty + i * 8][tx] = W[(size_t)(k0 + ty + i * 8) * DF + n0 + tx];
    __syncthreads();
#pragma unroll
    for (int i = 0; i < 4; i++) {
        int n = n0 + ty + i * 8;
        float v = t[tx][ty + i * 8];
        __nv_bfloat16 h = __float2bfloat16(v);
        __nv_bfloat16 l = __float2bfloat16(v - __bfloat162float(h));
        g_Whi[(size_t)n * D_IN + k0 + tx] = h;
        g_Wlo[(size_t)n * D_IN + k0 + tx] = l;
    }
}

__global__ __launch_bounds__(256) void k_asplit()
{
    size_t idx = ((size_t)blockIdx.x * 256 + threadIdx.x) * 4;
    float4 v = *(const float4*)&g_Ainv[idx];
    __nv_bfloat162 h01, h23, l01, l23;
    h01.x = __float2bfloat16(v.x);  l01.x = __float2bfloat16(v.x - __bfloat162float(h01.x));
    h01.y = __float2bfloat16(v.y);  l01.y = __float2bfloat16(v.y - __bfloat162float(h01.y));
    h23.x = __float2bfloat16(v.z);  l23.x = __float2bfloat16(v.z - __bfloat162float(h23.x));
    h23.y = __float2bfloat16(v.w);  l23.y = __float2bfloat16(v.w - __bfloat162float(h23.y));
    *(__nv_bfloat162*)&g_Bhi[idx]     = h01;
    *(__nv_bfloat162*)&g_Bhi[idx + 2] = h23;
    *(__nv_bfloat162*)&g_Blo[idx]     = l01;
    *(__nv_bfloat162*)&g_Blo[idx + 2] = l23;
}

// ---------------------------------------------------------------------------
// k_feats_mma: feats = relu(x @ W + b) via bf16x3 warp-MMA (unchanged from R7)
// ---------------------------------------------------------------------------
__global__ __launch_bounds__(256) void k_feats_mma(const float* __restrict__ bias)
{
    extern __shared__ char sm[];
    const uint32_t smb = smem_u32(sm);
    const int tid = threadIdx.x;
    const int lane = tid & 31;
    const int wid = tid >> 5;
    const int warp_m = wid >> 1;
    const int warp_n = wid & 1;
    const int b0 = blockIdx.x * 128;
    const int n0 = blockIdx.y * 64;

    const __nv_bfloat16* fh = g_xhi + (size_t)b0 * D_IN;
    const __nv_bfloat16* fl = g_xlo + (size_t)b0 * D_IN;
    const __nv_bfloat16* ah = g_Whi + (size_t)n0 * D_IN;
    const __nv_bfloat16* al = g_Wlo + (size_t)n0 * D_IN;

    const int aRow[2] = { warp_m * 32 +  0 + (lane & 7) + ((lane >> 3) & 1) * 8,
                          warp_m * 32 + 16 + (lane & 7) + ((lane >> 3) & 1) * 8 };
    const int aG = (lane >> 4) & 1;
    const int bRow[2] = { warp_n * 32 +  0 + (lane & 7) + ((lane >> 4) & 1) * 8,
                          warp_n * 32 + 16 + (lane & 7) + ((lane >> 4) & 1) * 8 };
    const int bG = (lane >> 3) & 1;
    const int aXor[2] = { aRow[0] & 7, aRow[1] & 7 };
    const int bXor[2] = { bRow[0] & 7, bRow[1] & 7 };

    auto stage = [&](int j) {
        const uint32_t sb = smb + (uint32_t)(j & 1) * STG_SZ;
        const int k0 = j * 64;
#pragma unroll
        for (int it = 0; it < 4; it++) {
            int slot = tid + it * 256;
            int row = slot >> 3, g = slot & 7;
            uint32_t off = (uint32_t)(row * 128 + ((g ^ (row & 7)) << 4));
            const size_t so = (size_t)row * D_IN + k0 + g * 8;
            CP16(sb + STG_FHI + off, fh + so);
            CP16(sb + STG_FLO + off, fl + so);
        }
#pragma unroll
        for (int it = 0; it < 2; it++) {
            int slot = tid + it * 256;
            int row = slot >> 3, g = slot & 7;
            uint32_t off = (uint32_t)(row * 128 + ((g ^ (row & 7)) << 4));
            const size_t so = (size_t)row * D_IN + k0 + g * 8;
            CP16(sb + STG_AHI + off, ah + so);
            CP16(sb + STG_ALO + off, al + so);
        }
        CP_COMMIT();
    };

    float acc[2][4][4];
#pragma unroll
    for (int mt = 0; mt < 2; mt++)
#pragma unroll
        for (int nt = 0; nt < 4; nt++)
#pragma unroll
            for (int r = 0; r < 4; r++) acc[mt][nt][r] = 0.f;

    stage(0);
#pragma unroll 1
    for (int ci = 0; ci < 16; ci++) {
        if (ci + 1 < 16) { stage(ci + 1); CP_WAIT1(); } else { CP_WAIT0(); }
        __syncthreads();
        const uint32_t sb = smb + (uint32_t)(ci & 1) * STG_SZ;
#pragma unroll
        for (int ks = 0; ks < 4; ks++) {
            uint32_t fa_hi[2][4], fa_lo[2][4], bm_hi[2][4], bm_lo[2][4];
#pragma unroll
            for (int mt = 0; mt < 2; mt++) {
                uint32_t ga = (uint32_t)(((ks * 2 + aG) ^ aXor[mt]) << 4);
                LDSM4(fa_hi[mt], sb + STG_FHI + aRow[mt] * 128 + ga);
                LDSM4(fa_lo[mt], sb + STG_FLO + aRow[mt] * 128 + ga);
            }
#pragma unroll
            for (int pr = 0; pr < 2; pr++) {
                uint32_t gb = (uint32_t)(((ks * 2 + bG) ^ bXor[pr]) << 4);
                LDSM4(bm_hi[pr], sb + STG_AHI + bRow[pr] * 128 + gb);
                LDSM4(bm_lo[pr], sb + STG_ALO + bRow[pr] * 128 + gb);
            }
#pragma unroll
            for (int mt = 0; mt < 2; mt++)
#pragma unroll
                for (int nt = 0; nt < 4; nt++) {
                    uint32_t* bh2 = &bm_hi[nt >> 1][(nt & 1) * 2];
                    uint32_t* bl2 = &bm_lo[nt >> 1][(nt & 1) * 2];
                    MMA16816(acc[mt][nt], fa_hi[mt], bh2);
                    MMA16816(acc[mt][nt], fa_hi[mt], bl2);
                    MMA16816(acc[mt][nt], fa_lo[mt], bh2);
                }
        }
        __syncthreads();
    }

#pragma unroll
    for (int nt = 0; nt < 4; nt++) {
        int c = n0 + warp_n * 32 + nt * 8 + (lane & 3) * 2;
        float bc0 = bias[c], bc1 = bias[c + 1];
#pragma unroll
        for (int mt = 0; mt < 2; mt++) {
#pragma unroll
            for (int half = 0; half < 2; half++) {
                int row = b0 + warp_m * 32 + mt * 16 + (lane >> 2) + half * 8;
                float v0 = acc[mt][nt][half * 2 + 0] + bc0;
                float v1 = acc[mt][nt][half * 2 + 1] + bc1;
                v0 = v0 > 0.f ? v0 : 0.f;
                v1 = v1 > 0.f ? v1 : 0.f;
                __nv_bfloat162 h2, l2;
                h2.x = __float2bfloat16(v0); l2.x = __float2bfloat16(v0 - __bfloat162float(h2.x));
                h2.y = __float2bfloat16(v1); l2.y = __float2bfloat16(v1 - __bfloat162float(h2.y));
                *(__nv_bfloat162*)&g_fhi[(size_t)row * DF + c] = h2;
                *(__nv_bfloat162*)&g_flo[(size_t)row * DF + c] = l2;
            }
        }
    }
}

// ---------------------------------------------------------------------------
// Kernel: triangular inverse of L = tril(covs[mk]) -> g_Ainv (upper zeroed)
// ---------------------------------------------------------------------------
__global__ __launch_bounds__(256) void k_trinv(const float* __restrict__ covs)
{
    const int mk = blockIdx.x;
    const int cg = blockIdx.y;
    const int w = threadIdx.x >> 5;
    const int lane = threadIdx.x & 31;
    const int g = w * 8 + cg;
    const int j0 = g * 4;

    const float* L = covs + (size_t)mk * DF * DF;
    float* Ai = g_Ainv + (size_t)mk * DF * DF;

    __shared__ float4 xck[8][DF];
    float4* xc = xck[w];

    for (int i = lane; i < j0; i += 32)
        *(float4*)&Ai[i * DF + j0] = make_float4(0.f, 0.f, 0.f, 0.f);

    for (int i = j0; i < DF; i++) {
        float4 s = make_float4(0.f, 0.f, 0.f, 0.f);
        for (int k = j0 + lane; k < i; k += 32) {
            float lik = L[i * DF + k];
            float4 xv = xc[k];
            s.x = fmaf(lik, xv.x, s.x);
            s.y = fmaf(lik, xv.y, s.y);
            s.z = fmaf(lik, xv.z, s.z);
            s.w = fmaf(lik, xv.w, s.w);
        }
#pragma unroll
        for (int off = 16; off > 0; off >>= 1) {
            s.x += __shfl_xor_sync(0xFFFFFFFFu, s.x, off);
            s.y += __shfl_xor_sync(0xFFFFFFFFu, s.y, off);
            s.z += __shfl_xor_sync(0xFFFFFFFFu, s.z, off);
            s.w += __shfl_xor_sync(0xFFFFFFFFu, s.w, off);
        }
        if (lane == 0) {
            float inv = 1.0f / L[i * DF + i];
            float4 xr;
            xr.x = ((i == j0 + 0 ? 1.0f : 0.0f) - s.x) * inv;
            xr.y = ((i == j0 + 1 ? 1.0f : 0.0f) - s.y) * inv;
            xr.z = ((i == j0 + 2 ? 1.0f : 0.0f) - s.z) * inv;
            xr.w = ((i == j0 + 3 ? 1.0f : 0.0f) - s.w) * inv;
            xc[i] = xr;
            *(float4*)&Ai[i * DF + j0] = xr;
        }
        __syncwarp();
    }
}

// ---------------------------------------------------------------------------
// Kernel: v[mk][d] = sum_k Ainv[mk][d][k] * mean[mk][k]  (grid (80,4))
// ---------------------------------------------------------------------------
__global__ __launch_bounds__(256) void k_vprep(const float* __restrict__ means)
{
    const int mk = blockIdx.x;
    const int d0 = blockIdx.y * 64;
    const int tid = threadIdx.x;
    const int w = tid >> 5;
    const int lane = tid & 31;
    __shared__ float ms[DF];
    ms[tid] = means[mk * DF + tid];
    __syncthreads();
    const float* Ai = g_Ainv + (size_t)mk * DF * DF;
    for (int d = d0 + w; d < d0 + 64; d += 8) {
        float s = 0.0f;
        for (int k = lane; k < DF; k += 32)
            s = fmaf(Ai[d * DF + k], ms[k], s);
#pragma unroll
        for (int off = 16; off > 0; off >>= 1)
            s += __shfl_xor_sync(0xFFFFFFFFu, s, off);
        if (lane == 0) g_v[mk * DF + d] = s;
    }
}

// ---------------------------------------------------------------------------
// Kernel: per-component constants, one warp per mk (grid 80, block 32)
// ---------------------------------------------------------------------------
__global__ __launch_bounds__(32) void k_prep(const float* __restrict__ covs,
                                             const float* __restrict__ weights)
{
    const int mk = blockIdx.x;
    const int lane = threadIdx.x;
    const float* L = covs + (size_t)mk * DF * DF;
    float logdet = 0.0f;
    for (int i = lane; i < DF; i += 32)
        logdet += logf(L[i * DF + i]);
#pragma unroll
    for (int off = 16; off > 0; off >>= 1)
        logdet += __shfl_xor_sync(0xFFFFFFFFu, logdet, off);
    if (lane == 0) {
        const int m = mk >> 3;
        float wk[NK];
        float mx = -1e30f;
#pragma unroll
        for (int j = 0; j < NK; j++) { wk[j] = weights[m * NK + j]; mx = fmaxf(mx, wk[j]); }
        float sum = 0.f;
#pragma unroll
        for (int j = 0; j < NK; j++) sum += expf(wk[j] - mx);
        float wsm = expf(weights[mk] - mx) / sum;
        g_c1[mk] = -0.5f * wsm;
        g_c2[mk] = wsm * (-0.5f * (float)DF * LOG2PI_F) - wsm * logdet;
    }
}

// ---------------------------------------------------------------------------
// Kernel (hot): warp-MMA bf16x3 GEMM + fused Mahalanobis epilogue.
// 512 threads, M=256 b-tile, 8(m)x2(n) warps, 2x80KB cp.async stages,
// fine-grained triangular skip in diagonal chunks.
// ---------------------------------------------------------------------------
__global__ __launch_bounds__(512) void k_quad_mma(float* __restrict__ out)
{
    extern __shared__ char sm[];
    const uint32_t smb = smem_u32(sm);
    const int tid = threadIdx.x;
    const int lane = tid & 31;
    const int wid = tid >> 5;
    const int warp_m = wid & 7;       // 0..7 (32 batch rows each -> M=256)
    const int warp_n = wid >> 3;      // 0..1 (32 d cols each), SMSP-balanced
    const int mk = blockIdx.y;
    const int b0 = blockIdx.x * 256;

    if (tid < 256) ((float*)(sm + OFQ2_V))[tid] = g_v[mk * DF + tid];

    const __nv_bfloat16* fh = g_fhi + (size_t)b0 * DF;
    const __nv_bfloat16* fl = g_flo + (size_t)b0 * DF;
    const __nv_bfloat16* ah = g_Bhi + (size_t)mk * DF * DF;
    const __nv_bfloat16* al = g_Blo + (size_t)mk * DF * DF;

    const int aRow[2] = { warp_m * 32 +  0 + (lane & 7) + ((lane >> 3) & 1) * 8,
                          warp_m * 32 + 16 + (lane & 7) + ((lane >> 3) & 1) * 8 };
    const int aG = (lane >> 4) & 1;
    const int bRow[2] = { warp_n * 32 +  0 + (lane & 7) + ((lane >> 4) & 1) * 8,
                          warp_n * 32 + 16 + (lane & 7) + ((lane >> 4) & 1) * 8 };
    const int bG = (lane >> 3) & 1;
    const int aXor[2] = { aRow[0] & 7, aRow[1] & 7 };
    const int bXor[2] = { bRow[0] & 7, bRow[1] & 7 };
    const int nlim = warp_n * 32;

    auto stage = [&](int j) {
        const uint32_t sb = smb + (uint32_t)(j & 1) * STG2_SZ;
        const int k0 = c_CK[j] * 64;
        const int ar0 = c_CD[j] * 64;
        // F: 256 rows x 8 groups of 16B (hi+lo)
#pragma unroll
        for (int it = 0; it < 4; it++) {
            int slot = tid + it * 512;
            int row = slot >> 3, g = slot & 7;
            uint32_t off = (uint32_t)(row * 128 + ((g ^ (row & 7)) << 4));
            const size_t so = (size_t)row * DF + k0 + g * 8;
            CP16(sb + ST2_FHI + off, fh + so);
            CP16(sb + ST2_FLO + off, fl + so);
        }
        // A: 64 rows x 8 groups
        {
            int row = tid >> 3, g = tid & 7;
            uint32_t off = (uint32_t)(row * 128 + ((g ^ (row & 7)) << 4));
            const size_t so = (size_t)(ar0 + row) * DF + k0 + g * 8;
            CP16(sb + ST2_AHI + off, ah + so);
            CP16(sb + ST2_ALO + off, al + so);
        }
        CP_COMMIT();
    };

    float qrow[4] = {0.f, 0.f, 0.f, 0.f};
    const float* vptr = (const float*)(sm + OFQ2_V);

    stage(0);
    int ci = 0;
#pragma unroll 1
    for (int dblk = 0; dblk < 4; dblk++) {
        const int nrow0 = dblk * 64;
        float acc[2][4][4];
#pragma unroll
        for (int mt = 0; mt < 2; mt++)
#pragma unroll
            for (int nt = 0; nt < 4; nt++)
#pragma unroll
                for (int r = 0; r < 4; r++) acc[mt][nt][r] = 0.f;

#pragma unroll 1
        for (int kc = 0; kc <= dblk; kc++) {
            if (ci + 1 < 10) { stage(ci + 1); CP_WAIT1(); } else { CP_WAIT0(); }
            __syncthreads();
            const uint32_t sb = smb + (uint32_t)(ci & 1) * STG2_SZ;
            const bool diag = (kc == dblk);
#pragma unroll
            for (int ks = 0; ks < 4; ks++) {
                uint32_t fa_hi[2][4], fa_lo[2][4], bm_hi[2][4], bm_lo[2][4];
                // fine triangular skip: in diagonal chunk, A[n][k]=0 for k>n
                const bool anyN = !diag || (ks * 16 <= nlim + 31);
                if (anyN) {
#pragma unroll
                    for (int mt = 0; mt < 2; mt++) {
                        uint32_t ga = (uint32_t)(((ks * 2 + aG) ^ aXor[mt]) << 4);
                        LDSM4(fa_hi[mt], sb + ST2_FHI + aRow[mt] * 128 + ga);
                        LDSM4(fa_lo[mt], sb + ST2_FLO + aRow[mt] * 128 + ga);
                    }
#pragma unroll
                    for (int pr = 0; pr < 2; pr++) {
                        if (!diag || (ks * 16 <= nlim + pr * 16 + 15)) {
                            uint32_t gb = (uint32_t)(((ks * 2 + bG) ^ bXor[pr]) << 4);
                            LDSM4(bm_hi[pr], sb + ST2_AHI + bRow[pr] * 128 + gb);
                            LDSM4(bm_lo[pr], sb + ST2_ALO + bRow[pr] * 128 + gb);
                        }
                    }
#pragma unroll
                    for (int mt = 0; mt < 2; mt++)
#pragma unroll
                        for (int nt = 0; nt < 4; nt++) {
                            if (!diag || (ks * 16 <= nlim + nt * 8 + 7)) {
                                uint32_t* bh2 = &bm_hi[nt >> 1][(nt & 1) * 2];
                                uint32_t* bl2 = &bm_lo[nt >> 1][(nt & 1) * 2];
                                MMA16816(acc[mt][nt], fa_hi[mt], bh2);
                                MMA16816(acc[mt][nt], fa_hi[mt], bl2);
                                MMA16816(acc[mt][nt], fa_lo[mt], bh2);
                            }
                        }
                }
            }
            __syncthreads();
            ci++;
        }

        // fold: z = D - v[d]; qrow += z^2
#pragma unroll
        for (int mt = 0; mt < 2; mt++)
#pragma unroll
            for (int nt = 0; nt < 4; nt++) {
#pragma unroll
                for (int r = 0; r < 4; r++) {
                    int d = nrow0 + warp_n * 32 + nt * 8 + (lane & 3) * 2 + (r & 1);
                    float z = acc[mt][nt][r] - vptr[d];
                    qrow[mt * 2 + (r >> 1)] = fmaf(z, z, qrow[mt * 2 + (r >> 1)]);
                }
            }
    }

    float* qs = (float*)(sm + OFQ2_Q);
#pragma unroll
    for (int i = 0; i < 4; i++) {
        float q = qrow[i];
        q += __shfl_xor_sync(0xFFFFFFFFu, q, 1);
        q += __shfl_xor_sync(0xFFFFFFFFu, q, 2);
        if ((lane & 3) == 0)
            qs[warp_n * 256 + warp_m * 32 + (i >> 1) * 16 + (i & 1) * 8 + (lane >> 2)] = q;
    }
    __syncthreads();
    if (tid < 256) {
        float tot = qs[tid] + qs[256 + tid];
        out[(size_t)(b0 + tid) * NMK + mk] = fmaf(g_c1[mk], tot, g_c2[mk]);
    }
}

// ---------------------------------------------------------------------------
extern "C" void kernel_launch(void* const* d_in, const int* in_sizes, int n_in,
                              void* d_out, int out_size)
{
    const float* x       = (const float*)d_in[0];
    const float* W       = (const float*)d_in[1];
    const float* bias    = (const float*)d_in[2];
    const float* means   = (const float*)d_in[3];
    const float* covs    = (const float*)d_in[4];
    const float* weights = (const float*)d_in[5];
    float* out = (float*)d_out;

    cudaFuncSetAttribute(k_quad_mma, cudaFuncAttributeMaxDynamicSharedMemorySize,
                         QUAD2_SMEM);
    cudaFuncSetAttribute(k_feats_mma, cudaFuncAttributeMaxDynamicSharedMemorySize,
                         2 * STG_SZ);

    k_xsplit<<<(BATCH * D_IN) / 1024, 256>>>(x);
    k_wsplit<<<dim3(D_IN / 32, DF / 32), 256>>>(W);
    k_trinv<<<dim3(NMK, 8), 256>>>(covs);
    k_feats_mma<<<dim3(BATCH / 128, DF / 64), 256, 2 * STG_SZ>>>(bias);
    k_asplit<<<(NMK * DF * DF) / 1024, 256>>>();
    k_vprep<<<dim3(NMK, 4), 256>>>(means);
    k_prep<<<NMK, 32>>>(covs, weights);
    k_quad_mma<<<dim3(BATCH / 256, NMK), 512, QUAD2_SMEM>>>(out);
}

// round 9
// speedup vs baseline: 1.0940x; 1.0940x over previous
#include <cuda_runtime.h>
#include <cuda_bf16.h>
#include <cstdint>
#include <math.h>

// Problem constants
#define BATCH 4096
#define D_IN  1024
#define DF    256
#define NM    10
#define NK    8
#define NMK   80
#define LOG2PI_F 1.8378770664093453f

// ---------------- scratch (no cudaMalloc allowed) ----------------
__device__ __align__(16) float          g_Ainv[NMK * DF * DF]; // fp32 L^-1 (upper zeroed)
__device__ __align__(16) __nv_bfloat16  g_xhi[BATCH * D_IN];   // x hi, [b][k]
__device__ __align__(16) __nv_bfloat16  g_xlo[BATCH * D_IN];   // x lo
__device__ __align__(16) __nv_bfloat16  g_Whi[DF * D_IN];      // W^T hi, [n][k]
__device__ __align__(16) __nv_bfloat16  g_Wlo[DF * D_IN];      // W^T lo
__device__ __align__(16) __nv_bfloat16  g_fhi[BATCH * DF];     // feats hi, [b][d]
__device__ __align__(16) __nv_bfloat16  g_flo[BATCH * DF];     // feats lo
__device__ __align__(16) __nv_bfloat16  g_Bhi[NMK * DF * DF];  // Ainv hi, [mk][d][k]
__device__ __align__(16) __nv_bfloat16  g_Blo[NMK * DF * DF];  // Ainv lo
__device__ float g_v[NMK * DF];                                 // Ainv @ mean (fp32)
__device__ float g_c1[NMK];                                     // -0.5 * w
__device__ float g_c2[NMK];                                     // w*(-0.5*DF*log2pi) - w*logdet

// quad chunk schedule: 20 K=32 chunks, dblk-major
__constant__ int c_CD3[20] = {0,0, 1,1,1,1, 2,2,2,2,2,2, 3,3,3,3,3,3,3,3};
__constant__ int c_CK3[20] = {0,1, 0,1,2,3, 0,1,2,3,4,5, 0,1,2,3,4,5,6,7};

// ---------------- helpers ----------------
__device__ __forceinline__ uint32_t smem_u32(const void* p) {
    uint32_t a;
    asm("{ .reg .u64 t; cvta.to.shared.u64 t, %1; cvt.u32.u64 %0, t; }" : "=r"(a) : "l"(p));
    return a;
}

#define LDSM4(r, addr) \
    asm volatile("ldmatrix.sync.aligned.m8n8.x4.shared.b16 {%0,%1,%2,%3}, [%4];" \
        : "=r"((r)[0]), "=r"((r)[1]), "=r"((r)[2]), "=r"((r)[3]) : "r"(addr))

#define MMA16816(d, a, b) \
    asm volatile("mma.sync.aligned.m16n8k16.row.col.f32.bf16.bf16.f32 " \
        "{%0,%1,%2,%3},{%4,%5,%6,%7},{%8,%9},{%0,%1,%2,%3};" \
        : "+f"((d)[0]), "+f"((d)[1]), "+f"((d)[2]), "+f"((d)[3]) \
        : "r"((a)[0]), "r"((a)[1]), "r"((a)[2]), "r"((a)[3]), "r"((b)[0]), "r"((b)[1]))

#define CP16(saddr, gptr) \
    asm volatile("cp.async.cg.shared.global [%0], [%1], 16;" :: "r"(saddr), "l"(gptr) : "memory")
#define CP_COMMIT() asm volatile("cp.async.commit_group;" ::: "memory")
#define CP_WAIT2()  asm volatile("cp.async.wait_group 2;" ::: "memory")
#define CP_WAIT1()  asm volatile("cp.async.wait_group 1;" ::: "memory")
#define CP_WAIT0()  asm volatile("cp.async.wait_group 0;" ::: "memory")

// feats stage buffer (48 KB per stage)
#define STG_SZ   49152
#define STG_FHI  0
#define STG_FLO  16384
#define STG_AHI  32768
#define STG_ALO  40960

// quad stage buffer (32 KB per stage), K=32, pair-packed 128B rows:
//   Fhi 64x128B @0, Flo @8192, A[mk][half] 32x128B @16384 + mk*8192 + half*4096
#define STG3_SZ  32768
#define ST3_FHI  0
#define ST3_FLO  8192
#define ST3_A    16384
#define OFQ3_V   (3 * STG3_SZ)            // 512 floats (v for 2 mk)
#define OFQ3_Q   (3 * STG3_SZ + 2048)     // 256 floats
#define QUAD3_SMEM (3 * STG3_SZ + 3072)   // 101376

// ---------------------------------------------------------------------------
// split kernels
// ---------------------------------------------------------------------------
__global__ __launch_bounds__(256) void k_xsplit(const float* __restrict__ x)
{
    size_t idx = ((size_t)blockIdx.x * 256 + threadIdx.x) * 4;
    float4 v = *(const float4*)&x[idx];
    __nv_bfloat162 h01, h23, l01, l23;
    h01.x = __float2bfloat16(v.x);  l01.x = __float2bfloat16(v.x - __bfloat162float(h01.x));
    h01.y = __float2bfloat16(v.y);  l01.y = __float2bfloat16(v.y - __bfloat162float(h01.y));
    h23.x = __float2bfloat16(v.z);  l23.x = __float2bfloat16(v.z - __bfloat162float(h23.x));
    h23.y = __float2bfloat16(v.w);  l23.y = __float2bfloat16(v.w - __bfloat162float(h23.y));
    *(__nv_bfloat162*)&g_xhi[idx]     = h01;
    *(__nv_bfloat162*)&g_xhi[idx + 2] = h23;
    *(__nv_bfloat162*)&g_xlo[idx]     = l01;
    *(__nv_bfloat162*)&g_xlo[idx + 2] = l23;
}

// W [k][n] fp32 -> W^T [n][k] bf16 hi/lo via smem 32x32 transpose
__global__ __launch_bounds__(256) void k_wsplit(const float* __restrict__ W)
{
    __shared__ float t[32][33];
    const int k0 = blockIdx.x * 32;
    const int n0 = blockIdx.y * 32;
    const int tx = threadIdx.x & 31, ty = threadIdx.x >> 5;
#pragma unroll
    for (int i = 0; i < 4; i++)
        t[ty + i * 8][tx] = W[(size_t)(k0 + ty + i * 8) * DF + n0 + tx];
    __syncthreads();
#pragma unroll
    for (int i = 0; i < 4; i++) {
        int n = n0 + ty + i * 8;
        float v = t[tx][ty + i * 8];
        __nv_bfloat16 h = __float2bfloat16(v);
        __nv_bfloat16 l = __float2bfloat16(v - __bfloat162float(h));
        g_Whi[(size_t)n * D_IN + k0 + tx] = h;
        g_Wlo[(size_t)n * D_IN + k0 + tx] = l;
    }
}

__global__ __launch_bounds__(256) void k_asplit()
{
    size_t idx = ((size_t)blockIdx.x * 256 + threadIdx.x) * 4;
    float4 v = *(const float4*)&g_Ainv[idx];
    __nv_bfloat162 h01, h23, l01, l23;
    h01.x = __float2bfloat16(v.x);  l01.x = __float2bfloat16(v.x - __bfloat162float(h01.x));
    h01.y = __float2bfloat16(v.y);  l01.y = __float2bfloat16(v.y - __bfloat162float(h01.y));
    h23.x = __float2bfloat16(v.z);  l23.x = __float2bfloat16(v.z - __bfloat162float(h23.x));
    h23.y = __float2bfloat16(v.w);  l23.y = __float2bfloat16(v.w - __bfloat162float(h23.y));
    *(__nv_bfloat162*)&g_Bhi[idx]     = h01;
    *(__nv_bfloat162*)&g_Bhi[idx + 2] = h23;
    *(__nv_bfloat162*)&g_Blo[idx]     = l01;
    *(__nv_bfloat162*)&g_Blo[idx + 2] = l23;
}

// ---------------------------------------------------------------------------
// k_feats_mma: feats = relu(x @ W + b) via bf16x3 warp-MMA (unchanged)
// ---------------------------------------------------------------------------
__global__ __launch_bounds__(256) void k_feats_mma(const float* __restrict__ bias)
{
    extern __shared__ char sm[];
    const uint32_t smb = smem_u32(sm);
    const int tid = threadIdx.x;
    const int lane = tid & 31;
    const int wid = tid >> 5;
    const int warp_m = wid >> 1;
    const int warp_n = wid & 1;
    const int b0 = blockIdx.x * 128;
    const int n0 = blockIdx.y * 64;

    const __nv_bfloat16* fh = g_xhi + (size_t)b0 * D_IN;
    const __nv_bfloat16* fl = g_xlo + (size_t)b0 * D_IN;
    const __nv_bfloat16* ah = g_Whi + (size_t)n0 * D_IN;
    const __nv_bfloat16* al = g_Wlo + (size_t)n0 * D_IN;

    const int aRow[2] = { warp_m * 32 +  0 + (lane & 7) + ((lane >> 3) & 1) * 8,
                          warp_m * 32 + 16 + (lane & 7) + ((lane >> 3) & 1) * 8 };
    const int aG = (lane >> 4) & 1;
    const int bRow[2] = { warp_n * 32 +  0 + (lane & 7) + ((lane >> 4) & 1) * 8,
                          warp_n * 32 + 16 + (lane & 7) + ((lane >> 4) & 1) * 8 };
    const int bG = (lane >> 3) & 1;
    const int aXor[2] = { aRow[0] & 7, aRow[1] & 7 };
    const int bXor[2] = { bRow[0] & 7, bRow[1] & 7 };

    auto stage = [&](int j) {
        const uint32_t sb = smb + (uint32_t)(j & 1) * STG_SZ;
        const int k0 = j * 64;
#pragma unroll
        for (int it = 0; it < 4; it++) {
            int slot = tid + it * 256;
            int row = slot >> 3, g = slot & 7;
            uint32_t off = (uint32_t)(row * 128 + ((g ^ (row & 7)) << 4));
            const size_t so = (size_t)row * D_IN + k0 + g * 8;
            CP16(sb + STG_FHI + off, fh + so);
            CP16(sb + STG_FLO + off, fl + so);
        }
#pragma unroll
        for (int it = 0; it < 2; it++) {
            int slot = tid + it * 256;
            int row = slot >> 3, g = slot & 7;
            uint32_t off = (uint32_t)(row * 128 + ((g ^ (row & 7)) << 4));
            const size_t so = (size_t)row * D_IN + k0 + g * 8;
            CP16(sb + STG_AHI + off, ah + so);
            CP16(sb + STG_ALO + off, al + so);
        }
        CP_COMMIT();
    };

    float acc[2][4][4];
#pragma unroll
    for (int mt = 0; mt < 2; mt++)
#pragma unroll
        for (int nt = 0; nt < 4; nt++)
#pragma unroll
            for (int r = 0; r < 4; r++) acc[mt][nt][r] = 0.f;

    stage(0);
#pragma unroll 1
    for (int ci = 0; ci < 16; ci++) {
        if (ci + 1 < 16) { stage(ci + 1); CP_WAIT1(); } else { CP_WAIT0(); }
        __syncthreads();
        const uint32_t sb = smb + (uint32_t)(ci & 1) * STG_SZ;
#pragma unroll
        for (int ks = 0; ks < 4; ks++) {
            uint32_t fa_hi[2][4], fa_lo[2][4], bm_hi[2][4], bm_lo[2][4];
#pragma unroll
            for (int mt = 0; mt < 2; mt++) {
                uint32_t ga = (uint32_t)(((ks * 2 + aG) ^ aXor[mt]) << 4);
                LDSM4(fa_hi[mt], sb + STG_FHI + aRow[mt] * 128 + ga);
                LDSM4(fa_lo[mt], sb + STG_FLO + aRow[mt] * 128 + ga);
            }
#pragma unroll
            for (int pr = 0; pr < 2; pr++) {
                uint32_t gb = (uint32_t)(((ks * 2 + bG) ^ bXor[pr]) << 4);
                LDSM4(bm_hi[pr], sb + STG_AHI + bRow[pr] * 128 + gb);
                LDSM4(bm_lo[pr], sb + STG_ALO + bRow[pr] * 128 + gb);
            }
#pragma unroll
            for (int mt = 0; mt < 2; mt++)
#pragma unroll
                for (int nt = 0; nt < 4; nt++) {
                    uint32_t* bh2 = &bm_hi[nt >> 1][(nt & 1) * 2];
                    uint32_t* bl2 = &bm_lo[nt >> 1][(nt & 1) * 2];
                    MMA16816(acc[mt][nt], fa_hi[mt], bh2);
                    MMA16816(acc[mt][nt], fa_hi[mt], bl2);
                    MMA16816(acc[mt][nt], fa_lo[mt], bh2);
                }
        }
        __syncthreads();
    }

#pragma unroll
    for (int nt = 0; nt < 4; nt++) {
        int c = n0 + warp_n * 32 + nt * 8 + (lane & 3) * 2;
        float bc0 = bias[c], bc1 = bias[c + 1];
#pragma unroll
        for (int mt = 0; mt < 2; mt++) {
#pragma unroll
            for (int half = 0; half < 2; half++) {
                int row = b0 + warp_m * 32 + mt * 16 + (lane >> 2) + half * 8;
                float v0 = acc[mt][nt][half * 2 + 0] + bc0;
                float v1 = acc[mt][nt][half * 2 + 1] + bc1;
                v0 = v0 > 0.f ? v0 : 0.f;
                v1 = v1 > 0.f ? v1 : 0.f;
                __nv_bfloat162 h2, l2;
                h2.x = __float2bfloat16(v0); l2.x = __float2bfloat16(v0 - __bfloat162float(h2.x));
                h2.y = __float2bfloat16(v1); l2.y = __float2bfloat16(v1 - __bfloat162float(h2.y));
                *(__nv_bfloat162*)&g_fhi[(size_t)row * DF + c] = h2;
                *(__nv_bfloat162*)&g_flo[(size_t)row * DF + c] = l2;
            }
        }
    }
}

// ---------------------------------------------------------------------------
// Kernel: triangular inverse of L = tril(covs[mk]) -> g_Ainv (upper zeroed)
// ---------------------------------------------------------------------------
__global__ __launch_bounds__(256) void k_trinv(const float* __restrict__ covs)
{
    const int mk = blockIdx.x;
    const int cg = blockIdx.y;
    const int w = threadIdx.x >> 5;
    const int lane = threadIdx.x & 31;
    const int g = w * 8 + cg;
    const int j0 = g * 4;

    const float* L = covs + (size_t)mk * DF * DF;
    float* Ai = g_Ainv + (size_t)mk * DF * DF;

    __shared__ float4 xck[8][DF];
    float4* xc = xck[w];

    for (int i = lane; i < j0; i += 32)
        *(float4*)&Ai[i * DF + j0] = make_float4(0.f, 0.f, 0.f, 0.f);

    for (int i = j0; i < DF; i++) {
        float4 s = make_float4(0.f, 0.f, 0.f, 0.f);
        for (int k = j0 + lane; k < i; k += 32) {
            float lik = L[i * DF + k];
            float4 xv = xc[k];
            s.x = fmaf(lik, xv.x, s.x);
            s.y = fmaf(lik, xv.y, s.y);
            s.z = fmaf(lik, xv.z, s.z);
            s.w = fmaf(lik, xv.w, s.w);
        }
#pragma unroll
        for (int off = 16; off > 0; off >>= 1) {
            s.x += __shfl_xor_sync(0xFFFFFFFFu, s.x, off);
            s.y += __shfl_xor_sync(0xFFFFFFFFu, s.y, off);
            s.z += __shfl_xor_sync(0xFFFFFFFFu, s.z, off);
            s.w += __shfl_xor_sync(0xFFFFFFFFu, s.w, off);
        }
        if (lane == 0) {
            float inv = 1.0f / L[i * DF + i];
            float4 xr;
            xr.x = ((i == j0 + 0 ? 1.0f : 0.0f) - s.x) * inv;
            xr.y = ((i == j0 + 1 ? 1.0f : 0.0f) - s.y) * inv;
            xr.z = ((i == j0 + 2 ? 1.0f : 0.0f) - s.z) * inv;
            xr.w = ((i == j0 + 3 ? 1.0f : 0.0f) - s.w) * inv;
            xc[i] = xr;
            *(float4*)&Ai[i * DF + j0] = xr;
        }
        __syncwarp();
    }
}

// ---------------------------------------------------------------------------
// Kernel: v[mk][d] = sum_k Ainv[mk][d][k] * mean[mk][k]  (grid (80,4))
// ---------------------------------------------------------------------------
__global__ __launch_bounds__(256) void k_vprep(const float* __restrict__ means)
{
    const int mk = blockIdx.x;
    const int d0 = blockIdx.y * 64;
    const int tid = threadIdx.x;
    const int w = tid >> 5;
    const int lane = tid & 31;
    __shared__ float ms[DF];
    ms[tid] = means[mk * DF + tid];
    __syncthreads();
    const float* Ai = g_Ainv + (size_t)mk * DF * DF;
    for (int d = d0 + w; d < d0 + 64; d += 8) {
        float s = 0.0f;
        for (int k = lane; k < DF; k += 32)
            s = fmaf(Ai[d * DF + k], ms[k], s);
#pragma unroll
        for (int off = 16; off > 0; off >>= 1)
            s += __shfl_xor_sync(0xFFFFFFFFu, s, off);
        if (lane == 0) g_v[mk * DF + d] = s;
    }
}

// ---------------------------------------------------------------------------
// Kernel: per-component constants, one warp per mk (grid 80, block 32)
// ---------------------------------------------------------------------------
__global__ __launch_bounds__(32) void k_prep(const float* __restrict__ covs,
                                             const float* __restrict__ weights)
{
    const int mk = blockIdx.x;
    const int lane = threadIdx.x;
    const float* L = covs + (size_t)mk * DF * DF;
    float logdet = 0.0f;
    for (int i = lane; i < DF; i += 32)
        logdet += logf(L[i * DF + i]);
#pragma unroll
    for (int off = 16; off > 0; off >>= 1)
        logdet += __shfl_xor_sync(0xFFFFFFFFu, logdet, off);
    if (lane == 0) {
        const int m = mk >> 3;
        float wk[NK];
        float mx = -1e30f;
#pragma unroll
        for (int j = 0; j < NK; j++) { wk[j] = weights[m * NK + j]; mx = fmaxf(mx, wk[j]); }
        float sum = 0.f;
#pragma unroll
        for (int j = 0; j < NK; j++) sum += expf(wk[j] - mx);
        float wsm = expf(weights[mk] - mx) / sum;
        g_c1[mk] = -0.5f * wsm;
        g_c2[mk] = wsm * (-0.5f * (float)DF * LOG2PI_F) - wsm * logdet;
    }
}

// ---------------------------------------------------------------------------
// Kernel (hot): warp-MMA bf16x3 GEMM + fused Mahalanobis epilogue.
// M=128 batch rows x 2 mk per CTA (F staged once for both mk).
// K=32 chunks, pair-packed 128B smem rows, 3-stage cp.async, triangular skip.
// 8 warps: warp_m = wid>>1 (32 rows), warp_mk = wid&1.
// ---------------------------------------------------------------------------
__global__ __launch_bounds__(256, 2) void k_quad_mma(float* __restrict__ out)
{
    extern __shared__ char sm[];
    const uint32_t smb = smem_u32(sm);
    const int tid = threadIdx.x;
    const int lane = tid & 31;
    const int wid = tid >> 5;
    const int warp_m = wid >> 1;      // 0..3
    const int warp_mk = wid & 1;      // 0..1
    const int mk0 = blockIdx.y * 2;
    const int b0 = blockIdx.x * 128;

    // v for both mk into smem
    ((float*)(sm + OFQ3_V))[tid]       = g_v[mk0 * DF + tid];
    ((float*)(sm + OFQ3_V))[256 + tid] = g_v[(mk0 + 1) * DF + tid];

    const __nv_bfloat16* fh = g_fhi + (size_t)b0 * DF;
    const __nv_bfloat16* fl = g_flo + (size_t)b0 * DF;
    const __nv_bfloat16* ahp[2] = { g_Bhi + (size_t)mk0 * DF * DF,
                                    g_Bhi + (size_t)(mk0 + 1) * DF * DF };
    const __nv_bfloat16* alp[2] = { g_Blo + (size_t)mk0 * DF * DF,
                                    g_Blo + (size_t)(mk0 + 1) * DF * DF };

    // ldmatrix per-lane addressing (pair-packed rows: batch row r at smem row r>>1,
    // 64B half (r&1), group gg = (r&1)*4 + ks*2 + sel, swizzled gg ^ ((r>>1)&7))
    int sA[2], gA[2];
#pragma unroll
    for (int mt = 0; mt < 2; mt++) {
        int r = warp_m * 32 + mt * 16 + (lane & 7) + ((lane >> 3) & 1) * 8;
        sA[mt] = r >> 1;
        gA[mt] = (r & 1) * 4 + ((lane >> 4) & 1);
    }
    int sB[4], gB[4];
#pragma unroll
    for (int pr = 0; pr < 4; pr++) {
        int r = pr * 16 + (lane & 7) + ((lane >> 4) & 1) * 8;
        sB[pr] = r >> 1;
        gB[pr] = (r & 1) * 4 + ((lane >> 3) & 1);
    }
    const uint32_t abufHi = smb + ST3_A + (uint32_t)warp_mk * 8192;
    const uint32_t abufLo = abufHi + 4096;

    auto stage = [&](int j) {
        const uint32_t sb = smb + (uint32_t)(j % 3) * STG3_SZ;
        const int k0 = c_CK3[j] * 32;
        const int ar0 = c_CD3[j] * 64;
        const bool diag = (k0 == ar0 + 32);
        // F hi/lo: 64 smem rows x 8 groups, 2 slots/thread each
#pragma unroll
        for (int it = 0; it < 2; it++) {
            int u = tid + it * 256;            // 0..511
            int s = u >> 3, gg = u & 7;
            uint32_t off = (uint32_t)(s * 128 + ((gg ^ (s & 7)) << 4));
            int r = s * 2 + (gg >> 2);
            const size_t so = (size_t)r * DF + k0 + (gg & 3) * 8;
            CP16(sb + ST3_FHI + off, fh + so);
            CP16(sb + ST3_FLO + off, fl + so);
        }
        // A: 2 mk x hi/lo x (32 smem rows x 8 groups)
#pragma unroll
        for (int it = 0; it < 4; it++) {
            int u = tid + it * 256;            // 0..1023
            int mki = u >> 9;
            int half = (u >> 8) & 1;
            int v = u & 255;
            int s = v >> 3, gg = v & 7;
            int r = s * 2 + (gg >> 2);         // local A row 0..63
            if (!(diag && r < 32)) {           // skip all-zero rows in diag chunk
                uint32_t off = (uint32_t)(s * 128 + ((gg ^ (s & 7)) << 4));
                const __nv_bfloat16* src = half ? alp[mki] : ahp[mki];
                const size_t so = (size_t)(ar0 + r) * DF + k0 + (gg & 3) * 8;
                CP16(sb + ST3_A + mki * 8192 + half * 4096 + off, src + so);
            }
        }
        CP_COMMIT();
    };

    float qrow[4] = {0.f, 0.f, 0.f, 0.f};
    const float* vptr = (const float*)(sm + OFQ3_V) + warp_mk * DF;

    stage(0);
    stage(1);
    int ci = 0;
#pragma unroll 1
    for (int dblk = 0; dblk < 4; dblk++) {
        const int nrow0 = dblk * 64;
        const int nch = 2 * (dblk + 1);
        float acc[2][8][4];
#pragma unroll
        for (int mt = 0; mt < 2; mt++)
#pragma unroll
            for (int nt = 0; nt < 8; nt++)
#pragma unroll
                for (int r = 0; r < 4; r++) acc[mt][nt][r] = 0.f;

#pragma unroll 1
        for (int kc = 0; kc < nch; kc++) {
            if (ci + 2 < 20) stage(ci + 2);
            {
                int pending = 19 - ci;
                if (pending >= 2) CP_WAIT2();
                else if (pending == 1) CP_WAIT1();
                else CP_WAIT0();
            }
            __syncthreads();
            const uint32_t sb = smb + (uint32_t)(ci % 3) * STG3_SZ;
            const int prStart = (kc == nch - 1) ? 2 : 0;  // diag chunk: cols<32 zero
#pragma unroll
            for (int ks = 0; ks < 2; ks++) {
                uint32_t fa_hi[2][4], fa_lo[2][4];
#pragma unroll
                for (int mt = 0; mt < 2; mt++) {
                    uint32_t off = (uint32_t)(sA[mt] * 128 +
                        (((gA[mt] + ks * 2) ^ (sA[mt] & 7)) << 4));
                    LDSM4(fa_hi[mt], sb + ST3_FHI + off);
                    LDSM4(fa_lo[mt], sb + ST3_FLO + off);
                }
#pragma unroll
                for (int pr = 0; pr < 4; pr++) {
                    if (pr >= prStart) {
                        uint32_t bm_hi[4], bm_lo[4];
                        uint32_t offb = (uint32_t)(sB[pr] * 128 +
                            (((gB[pr] + ks * 2) ^ (sB[pr] & 7)) << 4));
                        LDSM4(bm_hi, abufHi + (offb + (uint32_t)((ci % 3) * STG3_SZ)));
                        LDSM4(bm_lo, abufLo + (offb + (uint32_t)((ci % 3) * STG3_SZ)));
#pragma unroll
                        for (int mt = 0; mt < 2; mt++)
#pragma unroll
                            for (int j2 = 0; j2 < 2; j2++) {
                                int nt = pr * 2 + j2;
                                MMA16816(acc[mt][nt], fa_hi[mt], &bm_hi[j2 * 2]);
                                MMA16816(acc[mt][nt], fa_hi[mt], &bm_lo[j2 * 2]);
                                MMA16816(acc[mt][nt], fa_lo[mt], &bm_hi[j2 * 2]);
                            }
                    }
                }
            }
            __syncthreads();
            ci++;
        }

        // fold: z = D - v[d]; qrow += z^2  (warp owns all 64 cols of its mk)
#pragma unroll
        for (int mt = 0; mt < 2; mt++)
#pragma unroll
            for (int nt = 0; nt < 8; nt++) {
#pragma unroll
                for (int r = 0; r < 4; r++) {
                    int d = nrow0 + nt * 8 + (lane & 3) * 2 + (r & 1);
                    float z = acc[mt][nt][r] - vptr[d];
                    qrow[mt * 2 + (r >> 1)] = fmaf(z, z, qrow[mt * 2 + (r >> 1)]);
                }
            }
    }

    float* qs = (float*)(sm + OFQ3_Q);
#pragma unroll
    for (int i = 0; i < 4; i++) {
        float q = qrow[i];
        q += __shfl_xor_sync(0xFFFFFFFFu, q, 1);
        q += __shfl_xor_sync(0xFFFFFFFFu, q, 2);
        if ((lane & 3) == 0)
            qs[warp_mk * 128 + warp_m * 32 + (i >> 1) * 16 + (i & 1) * 8 + (lane >> 2)] = q;
    }
    __syncthreads();
    {
        int mkloc = tid >> 7;
        int row = tid & 127;
        int mk = mk0 + mkloc;
        out[(size_t)(b0 + row) * NMK + mk] =
            fmaf(g_c1[mk], qs[mkloc * 128 + row], g_c2[mk]);
    }
}

// ---------------------------------------------------------------------------
extern "C" void kernel_launch(void* const* d_in, const int* in_sizes, int n_in,
                              void* d_out, int out_size)
{
    const float* x       = (const float*)d_in[0];
    const float* W       = (const float*)d_in[1];
    const float* bias    = (const float*)d_in[2];
    const float* means   = (const float*)d_in[3];
    const float* covs    = (const float*)d_in[4];
    const float* weights = (const float*)d_in[5];
    float* out = (float*)d_out;

    cudaFuncSetAttribute(k_quad_mma, cudaFuncAttributeMaxDynamicSharedMemorySize,
                         QUAD3_SMEM);
    cudaFuncSetAttribute(k_feats_mma, cudaFuncAttributeMaxDynamicSharedMemorySize,
                         2 * STG_SZ);

    k_xsplit<<<(BATCH * D_IN) / 1024, 256>>>(x);
    k_wsplit<<<dim3(D_IN / 32, DF / 32), 256>>>(W);
    k_trinv<<<dim3(NMK, 8), 256>>>(covs);
    k_feats_mma<<<dim3(BATCH / 128, DF / 64), 256, 2 * STG_SZ>>>(bias);
    k_asplit<<<(NMK * DF * DF) / 1024, 256>>>();
    k_vprep<<<dim3(NMK, 4), 256>>>(means);
    k_prep<<<NMK, 32>>>(covs, weights);
    k_quad_mma<<<dim3(BATCH / 128, NMK / 2), 256, QUAD3_SMEM>>>(out);
}

// round 10
// speedup vs baseline: 1.4462x; 1.3220x over previous
#include <cuda_runtime.h>
#include <cuda_fp16.h>
#include <cstdint>
#include <math.h>

// Problem constants
#define BATCH 4096
#define D_IN  1024
#define DF    256
#define NM    10
#define NK    8
#define NMK   80
#define LOG2PI_F 1.8378770664093453f

// ---------------- scratch (no cudaMalloc allowed) ----------------
__device__ __align__(16) float  g_Ainv[NMK * DF * DF]; // fp32 L^-1 (upper zeroed)
__device__ __align__(16) __half g_xh[BATCH * D_IN];    // x fp16, [b][k]
__device__ __align__(16) __half g_Wh[DF * D_IN];       // W^T fp16, [n][k]
__device__ __align__(16) __half g_fh[BATCH * DF];      // feats fp16, [b][d]
__device__ __align__(16) __half g_Bh[NMK * DF * DF];   // Ainv fp16, [mk][d][k]
__device__ float g_v[NMK * DF];                         // Ainv @ mean (fp32)
__device__ float g_c1[NMK];                             // -0.5 * w
__device__ float g_c2[NMK];                             // w*(-0.5*DF*log2pi) - w*logdet

// quad chunk schedule: 20 K=32 chunks, dblk-major
__constant__ int c_CD3[20] = {0,0, 1,1,1,1, 2,2,2,2,2,2, 3,3,3,3,3,3,3,3};
__constant__ int c_CK3[20] = {0,1, 0,1,2,3, 0,1,2,3,4,5, 0,1,2,3,4,5,6,7};

// ---------------- helpers ----------------
__device__ __forceinline__ uint32_t smem_u32(const void* p) {
    uint32_t a;
    asm("{ .reg .u64 t; cvta.to.shared.u64 t, %1; cvt.u32.u64 %0, t; }" : "=r"(a) : "l"(p));
    return a;
}

#define LDSM4(r, addr) \
    asm volatile("ldmatrix.sync.aligned.m8n8.x4.shared.b16 {%0,%1,%2,%3}, [%4];" \
        : "=r"((r)[0]), "=r"((r)[1]), "=r"((r)[2]), "=r"((r)[3]) : "r"(addr))

#define MMA16816(d, a, b) \
    asm volatile("mma.sync.aligned.m16n8k16.row.col.f32.f16.f16.f32 " \
        "{%0,%1,%2,%3},{%4,%5,%6,%7},{%8,%9},{%0,%1,%2,%3};" \
        : "+f"((d)[0]), "+f"((d)[1]), "+f"((d)[2]), "+f"((d)[3]) \
        : "r"((a)[0]), "r"((a)[1]), "r"((a)[2]), "r"((a)[3]), "r"((b)[0]), "r"((b)[1]))

#define CP16(saddr, gptr) \
    asm volatile("cp.async.cg.shared.global [%0], [%1], 16;" :: "r"(saddr), "l"(gptr) : "memory")
#define CP_COMMIT() asm volatile("cp.async.commit_group;" ::: "memory")
#define CP_WAIT2()  asm volatile("cp.async.wait_group 2;" ::: "memory")
#define CP_WAIT1()  asm volatile("cp.async.wait_group 1;" ::: "memory")
#define CP_WAIT0()  asm volatile("cp.async.wait_group 0;" ::: "memory")

// feats stage buffer (24 KB per stage): F 128x128B @0, W 64x128B @16384
#define STG_SZ   24576
#define STG_FH   0
#define STG_WH   16384

// quad stage buffer (16 KB per stage), K=32, pair-packed 128B rows:
//   F 64x128B @0, A[mk] 32x128B @8192 + mk*4096
#define STG3_SZ  16384
#define ST3_FH   0
#define ST3_A    8192
#define OFQ3_V   (3 * STG3_SZ)            // 49152: 512 floats (v for 2 mk)
#define OFQ3_Q   (3 * STG3_SZ + 2048)     // 51200: 256 floats
#define QUAD3_SMEM (3 * STG3_SZ + 3072)   // 52224

// ---------------------------------------------------------------------------
// split kernels (fp32 -> fp16)
// ---------------------------------------------------------------------------
__global__ __launch_bounds__(256) void k_xsplit(const float* __restrict__ x)
{
    size_t idx = ((size_t)blockIdx.x * 256 + threadIdx.x) * 4;
    float4 v = *(const float4*)&x[idx];
    *(__half2*)&g_xh[idx]     = __floats2half2_rn(v.x, v.y);
    *(__half2*)&g_xh[idx + 2] = __floats2half2_rn(v.z, v.w);
}

// W [k][n] fp32 -> W^T [n][k] fp16 via smem 32x32 transpose
__global__ __launch_bounds__(256) void k_wsplit(const float* __restrict__ W)
{
    __shared__ float t[32][33];
    const int k0 = blockIdx.x * 32;
    const int n0 = blockIdx.y * 32;
    const int tx = threadIdx.x & 31, ty = threadIdx.x >> 5;
#pragma unroll
    for (int i = 0; i < 4; i++)
        t[ty + i * 8][tx] = W[(size_t)(k0 + ty + i * 8) * DF + n0 + tx];
    __syncthreads();
#pragma unroll
    for (int i = 0; i < 4; i++) {
        int n = n0 + ty + i * 8;
        g_Wh[(size_t)n * D_IN + k0 + tx] = __float2half_rn(t[tx][ty + i * 8]);
    }
}

__global__ __launch_bounds__(256) void k_asplit()
{
    size_t idx = ((size_t)blockIdx.x * 256 + threadIdx.x) * 4;
    float4 v = *(const float4*)&g_Ainv[idx];
    *(__half2*)&g_Bh[idx]     = __floats2half2_rn(v.x, v.y);
    *(__half2*)&g_Bh[idx + 2] = __floats2half2_rn(v.z, v.w);
}

// ---------------------------------------------------------------------------
// k_feats_mma: feats = relu(x @ W + b), single-pass fp16 warp-MMA.
// Grid (32 b-tiles, 4 n-tiles of 64), 256 threads, 2-stage cp.async.
// ---------------------------------------------------------------------------
__global__ __launch_bounds__(256) void k_feats_mma(const float* __restrict__ bias)
{
    extern __shared__ char sm[];
    const uint32_t smb = smem_u32(sm);
    const int tid = threadIdx.x;
    const int lane = tid & 31;
    const int wid = tid >> 5;
    const int warp_m = wid >> 1;
    const int warp_n = wid & 1;
    const int b0 = blockIdx.x * 128;
    const int n0 = blockIdx.y * 64;

    const __half* fh = g_xh + (size_t)b0 * D_IN;
    const __half* ah = g_Wh + (size_t)n0 * D_IN;

    const int aRow[2] = { warp_m * 32 +  0 + (lane & 7) + ((lane >> 3) & 1) * 8,
                          warp_m * 32 + 16 + (lane & 7) + ((lane >> 3) & 1) * 8 };
    const int aG = (lane >> 4) & 1;
    const int bRow[2] = { warp_n * 32 +  0 + (lane & 7) + ((lane >> 4) & 1) * 8,
                          warp_n * 32 + 16 + (lane & 7) + ((lane >> 4) & 1) * 8 };
    const int bG = (lane >> 3) & 1;
    const int aXor[2] = { aRow[0] & 7, aRow[1] & 7 };
    const int bXor[2] = { bRow[0] & 7, bRow[1] & 7 };

    auto stage = [&](int j) {
        const uint32_t sb = smb + (uint32_t)(j & 1) * STG_SZ;
        const int k0 = j * 64;
#pragma unroll
        for (int it = 0; it < 4; it++) {
            int slot = tid + it * 256;
            int row = slot >> 3, g = slot & 7;
            uint32_t off = (uint32_t)(row * 128 + ((g ^ (row & 7)) << 4));
            CP16(sb + STG_FH + off, fh + (size_t)row * D_IN + k0 + g * 8);
        }
#pragma unroll
        for (int it = 0; it < 2; it++) {
            int slot = tid + it * 256;
            int row = slot >> 3, g = slot & 7;
            uint32_t off = (uint32_t)(row * 128 + ((g ^ (row & 7)) << 4));
            CP16(sb + STG_WH + off, ah + (size_t)row * D_IN + k0 + g * 8);
        }
        CP_COMMIT();
    };

    float acc[2][4][4];
#pragma unroll
    for (int mt = 0; mt < 2; mt++)
#pragma unroll
        for (int nt = 0; nt < 4; nt++)
#pragma unroll
            for (int r = 0; r < 4; r++) acc[mt][nt][r] = 0.f;

    stage(0);
#pragma unroll 1
    for (int ci = 0; ci < 16; ci++) {
        if (ci + 1 < 16) { stage(ci + 1); CP_WAIT1(); } else { CP_WAIT0(); }
        __syncthreads();
        const uint32_t sb = smb + (uint32_t)(ci & 1) * STG_SZ;
#pragma unroll
        for (int ks = 0; ks < 4; ks++) {
            uint32_t fa[2][4], bm[2][4];
#pragma unroll
            for (int mt = 0; mt < 2; mt++) {
                uint32_t ga = (uint32_t)(((ks * 2 + aG) ^ aXor[mt]) << 4);
                LDSM4(fa[mt], sb + STG_FH + aRow[mt] * 128 + ga);
            }
#pragma unroll
            for (int pr = 0; pr < 2; pr++) {
                uint32_t gb = (uint32_t)(((ks * 2 + bG) ^ bXor[pr]) << 4);
                LDSM4(bm[pr], sb + STG_WH + bRow[pr] * 128 + gb);
            }
#pragma unroll
            for (int mt = 0; mt < 2; mt++)
#pragma unroll
                for (int nt = 0; nt < 4; nt++)
                    MMA16816(acc[mt][nt], fa[mt], &bm[nt >> 1][(nt & 1) * 2]);
        }
        __syncthreads();
    }

    // epilogue: bias + relu, fp16 store
#pragma unroll
    for (int nt = 0; nt < 4; nt++) {
        int c = n0 + warp_n * 32 + nt * 8 + (lane & 3) * 2;
        float bc0 = bias[c], bc1 = bias[c + 1];
#pragma unroll
        for (int mt = 0; mt < 2; mt++) {
#pragma unroll
            for (int half = 0; half < 2; half++) {
                int row = b0 + warp_m * 32 + mt * 16 + (lane >> 2) + half * 8;
                float v0 = acc[mt][nt][half * 2 + 0] + bc0;
                float v1 = acc[mt][nt][half * 2 + 1] + bc1;
                v0 = v0 > 0.f ? v0 : 0.f;
                v1 = v1 > 0.f ? v1 : 0.f;
                *(__half2*)&g_fh[(size_t)row * DF + c] = __floats2half2_rn(v0, v1);
            }
        }
    }
}

// ---------------------------------------------------------------------------
// Kernel: triangular inverse of L = tril(covs[mk]) -> g_Ainv (upper zeroed)
// ---------------------------------------------------------------------------
__global__ __launch_bounds__(256) void k_trinv(const float* __restrict__ covs)
{
    const int mk = blockIdx.x;
    const int cg = blockIdx.y;
    const int w = threadIdx.x >> 5;
    const int lane = threadIdx.x & 31;
    const int g = w * 8 + cg;
    const int j0 = g * 4;

    const float* L = covs + (size_t)mk * DF * DF;
    float* Ai = g_Ainv + (size_t)mk * DF * DF;

    __shared__ float4 xck[8][DF];
    float4* xc = xck[w];

    for (int i = lane; i < j0; i += 32)
        *(float4*)&Ai[i * DF + j0] = make_float4(0.f, 0.f, 0.f, 0.f);

    for (int i = j0; i < DF; i++) {
        float4 s = make_float4(0.f, 0.f, 0.f, 0.f);
        for (int k = j0 + lane; k < i; k += 32) {
            float lik = L[i * DF + k];
            float4 xv = xc[k];
            s.x = fmaf(lik, xv.x, s.x);
            s.y = fmaf(lik, xv.y, s.y);
            s.z = fmaf(lik, xv.z, s.z);
            s.w = fmaf(lik, xv.w, s.w);
        }
#pragma unroll
        for (int off = 16; off > 0; off >>= 1) {
            s.x += __shfl_xor_sync(0xFFFFFFFFu, s.x, off);
            s.y += __shfl_xor_sync(0xFFFFFFFFu, s.y, off);
            s.z += __shfl_xor_sync(0xFFFFFFFFu, s.z, off);
            s.w += __shfl_xor_sync(0xFFFFFFFFu, s.w, off);
        }
        if (lane == 0) {
            float inv = 1.0f / L[i * DF + i];
            float4 xr;
            xr.x = ((i == j0 + 0 ? 1.0f : 0.0f) - s.x) * inv;
            xr.y = ((i == j0 + 1 ? 1.0f : 0.0f) - s.y) * inv;
            xr.z = ((i == j0 + 2 ? 1.0f : 0.0f) - s.z) * inv;
            xr.w = ((i == j0 + 3 ? 1.0f : 0.0f) - s.w) * inv;
            xc[i] = xr;
            *(float4*)&Ai[i * DF + j0] = xr;
        }
        __syncwarp();
    }
}

// ---------------------------------------------------------------------------
// Kernel: v[mk][d] = sum_k Ainv[mk][d][k] * mean[mk][k]  (grid (80,4))
// ---------------------------------------------------------------------------
__global__ __launch_bounds__(256) void k_vprep(const float* __restrict__ means)
{
    const int mk = blockIdx.x;
    const int d0 = blockIdx.y * 64;
    const int tid = threadIdx.x;
    const int w = tid >> 5;
    const int lane = tid & 31;
    __shared__ float ms[DF];
    ms[tid] = means[mk * DF + tid];
    __syncthreads();
    const float* Ai = g_Ainv + (size_t)mk * DF * DF;
    for (int d = d0 + w; d < d0 + 64; d += 8) {
        float s = 0.0f;
        for (int k = lane; k < DF; k += 32)
            s = fmaf(Ai[d * DF + k], ms[k], s);
#pragma unroll
        for (int off = 16; off > 0; off >>= 1)
            s += __shfl_xor_sync(0xFFFFFFFFu, s, off);
        if (lane == 0) g_v[mk * DF + d] = s;
    }
}

// ---------------------------------------------------------------------------
// Kernel: per-component constants, one warp per mk (grid 80, block 32)
// ---------------------------------------------------------------------------
__global__ __launch_bounds__(32) void k_prep(const float* __restrict__ covs,
                                             const float* __restrict__ weights)
{
    const int mk = blockIdx.x;
    const int lane = threadIdx.x;
    const float* L = covs + (size_t)mk * DF * DF;
    float logdet = 0.0f;
    for (int i = lane; i < DF; i += 32)
        logdet += logf(L[i * DF + i]);
#pragma unroll
    for (int off = 16; off > 0; off >>= 1)
        logdet += __shfl_xor_sync(0xFFFFFFFFu, logdet, off);
    if (lane == 0) {
        const int m = mk >> 3;
        float wk[NK];
        float mx = -1e30f;
#pragma unroll
        for (int j = 0; j < NK; j++) { wk[j] = weights[m * NK + j]; mx = fmaxf(mx, wk[j]); }
        float sum = 0.f;
#pragma unroll
        for (int j = 0; j < NK; j++) sum += expf(wk[j] - mx);
        float wsm = expf(weights[mk] - mx) / sum;
        g_c1[mk] = -0.5f * wsm;
        g_c2[mk] = wsm * (-0.5f * (float)DF * LOG2PI_F) - wsm * logdet;
    }
}

// ---------------------------------------------------------------------------
// Kernel (hot): single-pass fp16 warp-MMA GEMM + fused Mahalanobis epilogue.
// M=128 batch rows x 2 mk per CTA. K=32 chunks pair-packed into 128B rows,
// 3-stage cp.async, triangular skip. 8 warps: warp_m = wid>>1, warp_mk = wid&1.
// ---------------------------------------------------------------------------
__global__ __launch_bounds__(256, 2) void k_quad_mma(float* __restrict__ out)
{
    extern __shared__ char sm[];
    const uint32_t smb = smem_u32(sm);
    const int tid = threadIdx.x;
    const int lane = tid & 31;
    const int wid = tid >> 5;
    const int warp_m = wid >> 1;      // 0..3
    const int warp_mk = wid & 1;      // 0..1
    const int mk0 = blockIdx.y * 2;
    const int b0 = blockIdx.x * 128;

    ((float*)(sm + OFQ3_V))[tid]       = g_v[mk0 * DF + tid];
    ((float*)(sm + OFQ3_V))[256 + tid] = g_v[(mk0 + 1) * DF + tid];

    const __half* fh = g_fh + (size_t)b0 * DF;
    const __half* ap[2] = { g_Bh + (size_t)mk0 * DF * DF,
                            g_Bh + (size_t)(mk0 + 1) * DF * DF };

    // pair-packed ldmatrix addressing: batch/A row r at smem row r>>1,
    // 64B half (r&1), group gg = (r&1)*4 + ks*2 + sel, swizzled gg ^ ((r>>1)&7)
    int sA[2], gA[2];
#pragma unroll
    for (int mt = 0; mt < 2; mt++) {
        int r = warp_m * 32 + mt * 16 + (lane & 7) + ((lane >> 3) & 1) * 8;
        sA[mt] = r >> 1;
        gA[mt] = (r & 1) * 4 + ((lane >> 4) & 1);
    }
    int sB[4], gB[4];
#pragma unroll
    for (int pr = 0; pr < 4; pr++) {
        int r = pr * 16 + (lane & 7) + ((lane >> 4) & 1) * 8;
        sB[pr] = r >> 1;
        gB[pr] = (r & 1) * 4 + ((lane >> 3) & 1);
    }
    const uint32_t abuf = smb + ST3_A + (uint32_t)warp_mk * 4096;

    auto stage = [&](int j) {
        const uint32_t sb = smb + (uint32_t)(j % 3) * STG3_SZ;
        const int k0 = c_CK3[j] * 32;
        const int ar0 = c_CD3[j] * 64;
        const bool diag = (k0 == ar0 + 32);
        // F: 64 smem rows x 8 groups = 512 slots
#pragma unroll
        for (int it = 0; it < 2; it++) {
            int u = tid + it * 256;
            int s = u >> 3, gg = u & 7;
            uint32_t off = (uint32_t)(s * 128 + ((gg ^ (s & 7)) << 4));
            int r = s * 2 + (gg >> 2);
            CP16(sb + ST3_FH + off, fh + (size_t)r * DF + k0 + (gg & 3) * 8);
        }
        // A: 2 mk x (32 smem rows x 8 groups) = 512 slots
#pragma unroll
        for (int it = 0; it < 2; it++) {
            int u = tid + it * 256;
            int mki = u >> 8;
            int v = u & 255;
            int s = v >> 3, gg = v & 7;
            int r = s * 2 + (gg >> 2);          // local A row 0..63
            if (!(diag && r < 32)) {            // skip all-zero rows in diag chunk
                uint32_t off = (uint32_t)(s * 128 + ((gg ^ (s & 7)) << 4));
                CP16(sb + ST3_A + mki * 4096 + off,
                     ap[mki] + (size_t)(ar0 + r) * DF + k0 + (gg & 3) * 8);
            }
        }
        CP_COMMIT();
    };

    float qrow[4] = {0.f, 0.f, 0.f, 0.f};
    const float* vptr = (const float*)(sm + OFQ3_V) + warp_mk * DF;

    stage(0);
    stage(1);
    int ci = 0;
#pragma unroll 1
    for (int dblk = 0; dblk < 4; dblk++) {
        const int nrow0 = dblk * 64;
        const int nch = 2 * (dblk + 1);
        float acc[2][8][4];
#pragma unroll
        for (int mt = 0; mt < 2; mt++)
#pragma unroll
            for (int nt = 0; nt < 8; nt++)
#pragma unroll
                for (int r = 0; r < 4; r++) acc[mt][nt][r] = 0.f;

#pragma unroll 1
        for (int kc = 0; kc < nch; kc++) {
            if (ci + 2 < 20) stage(ci + 2);
            {
                int pending = 19 - ci;
                if (pending >= 2) CP_WAIT2();
                else if (pending == 1) CP_WAIT1();
                else CP_WAIT0();
            }
            __syncthreads();
            const uint32_t sb = smb + (uint32_t)(ci % 3) * STG3_SZ;
            const int prStart = (kc == nch - 1) ? 2 : 0;  // diag chunk: rows<32 zero
#pragma unroll
            for (int ks = 0; ks < 2; ks++) {
                uint32_t fa[2][4];
#pragma unroll
                for (int mt = 0; mt < 2; mt++) {
                    uint32_t off = (uint32_t)(sA[mt] * 128 +
                        (((gA[mt] + ks * 2) ^ (sA[mt] & 7)) << 4));
                    LDSM4(fa[mt], sb + ST3_FH + off);
                }
#pragma unroll
                for (int pr = 0; pr < 4; pr++) {
                    if (pr >= prStart) {
                        uint32_t bm[4];
                        uint32_t offb = (uint32_t)(sB[pr] * 128 +
                            (((gB[pr] + ks * 2) ^ (sB[pr] & 7)) << 4));
                        LDSM4(bm, abuf + (uint32_t)((ci % 3) * STG3_SZ) + offb);
#pragma unroll
                        for (int mt = 0; mt < 2; mt++)
#pragma unroll
                            for (int j2 = 0; j2 < 2; j2++)
                                MMA16816(acc[mt][pr * 2 + j2], fa[mt], &bm[j2 * 2]);
                    }
                }
            }
            __syncthreads();
            ci++;
        }

        // fold: z = D - v[d]; qrow += z^2  (warp owns all 64 cols of its mk)
#pragma unroll
        for (int mt = 0; mt < 2; mt++)
#pragma unroll
            for (int nt = 0; nt < 8; nt++) {
#pragma unroll
                for (int r = 0; r < 4; r++) {
                    int d = nrow0 + nt * 8 + (lane & 3) * 2 + (r & 1);
                    float z = acc[mt][nt][r] - vptr[d];
                    qrow[mt * 2 + (r >> 1)] = fmaf(z, z, qrow[mt * 2 + (r >> 1)]);
                }
            }
    }

    float* qs = (float*)(sm + OFQ3_Q);
#pragma unroll
    for (int i = 0; i < 4; i++) {
        float q = qrow[i];
        q += __shfl_xor_sync(0xFFFFFFFFu, q, 1);
        q += __shfl_xor_sync(0xFFFFFFFFu, q, 2);
        if ((lane & 3) == 0)
            qs[warp_mk * 128 + warp_m * 32 + (i >> 1) * 16 + (i & 1) * 8 + (lane >> 2)] = q;
    }
    __syncthreads();
    {
        int mkloc = tid >> 7;
        int row = tid & 127;
        int mk = mk0 + mkloc;
        out[(size_t)(b0 + row) * NMK + mk] =
            fmaf(g_c1[mk], qs[mkloc * 128 + row], g_c2[mk]);
    }
}

// ---------------------------------------------------------------------------
extern "C" void kernel_launch(void* const* d_in, const int* in_sizes, int n_in,
                              void* d_out, int out_size)
{
    const float* x       = (const float*)d_in[0];
    const float* W       = (const float*)d_in[1];
    const float* bias    = (const float*)d_in[2];
    const float* means   = (const float*)d_in[3];
    const float* covs    = (const float*)d_in[4];
    const float* weights = (const float*)d_in[5];
    float* out = (float*)d_out;

    cudaFuncSetAttribute(k_quad_mma, cudaFuncAttributeMaxDynamicSharedMemorySize,
                         QUAD3_SMEM);
    cudaFuncSetAttribute(k_feats_mma, cudaFuncAttributeMaxDynamicSharedMemorySize,
                         2 * STG_SZ);

    k_xsplit<<<(BATCH * D_IN) / 1024, 256>>>(x);
    k_wsplit<<<dim3(D_IN / 32, DF / 32), 256>>>(W);
    k_trinv<<<dim3(NMK, 8), 256>>>(covs);
    k_feats_mma<<<dim3(BATCH / 128, DF / 64), 256, 2 * STG_SZ>>>(bias);
    k_asplit<<<(NMK * DF * DF) / 1024, 256>>>();
    k_vprep<<<dim3(NMK, 4), 256>>>(means);
    k_prep<<<NMK, 32>>>(covs, weights);
    k_quad_mma<<<dim3(BATCH / 128, NMK / 2), 256, QUAD3_SMEM>>>(out);
}

// round 11
// speedup vs baseline: 1.4608x; 1.0101x over previous
#include <cuda_runtime.h>
#include <cuda_fp16.h>
#include <cstdint>
#include <math.h>

// Problem constants
#define BATCH 4096
#define D_IN  1024
#define DF    256
#define NM    10
#define NK    8
#define NMK   80
#define LOG2PI_F 1.8378770664093453f

// ---------------- scratch (no cudaMalloc allowed) ----------------
__device__ __align__(16) float  g_Ainv[NMK * DF * DF]; // fp32 L^-1 (upper zeroed)
__device__ __align__(16) __half g_xh[BATCH * D_IN];    // x fp16, [b][k]
__device__ __align__(16) __half g_Wh[DF * D_IN];       // W^T fp16, [n][k]
__device__ __align__(16) __half g_fh[BATCH * DF];      // feats fp16, [b][d]
__device__ __align__(16) __half g_Bh[NMK * DF * DF];   // Ainv fp16, [mk][d][k]
__device__ float g_v[NMK * DF];                         // Ainv @ mean (fp32)
__device__ float g_c1[NMK];                             // -0.5 * w
__device__ float g_c2[NMK];                             // w*(-0.5*DF*log2pi) - w*logdet

// quad chunk schedule: 20 K=32 chunks, dblk-major
__constant__ int c_CD3[20] = {0,0, 1,1,1,1, 2,2,2,2,2,2, 3,3,3,3,3,3,3,3};
__constant__ int c_CK3[20] = {0,1, 0,1,2,3, 0,1,2,3,4,5, 0,1,2,3,4,5,6,7};

// ---------------- helpers ----------------
__device__ __forceinline__ uint32_t smem_u32(const void* p) {
    uint32_t a;
    asm("{ .reg .u64 t; cvta.to.shared.u64 t, %1; cvt.u32.u64 %0, t; }" : "=r"(a) : "l"(p));
    return a;
}

#define LDSM4(r, addr) \
    asm volatile("ldmatrix.sync.aligned.m8n8.x4.shared.b16 {%0,%1,%2,%3}, [%4];" \
        : "=r"((r)[0]), "=r"((r)[1]), "=r"((r)[2]), "=r"((r)[3]) : "r"(addr))

#define MMA16816(d, a, b) \
    asm volatile("mma.sync.aligned.m16n8k16.row.col.f32.f16.f16.f32 " \
        "{%0,%1,%2,%3},{%4,%5,%6,%7},{%8,%9},{%0,%1,%2,%3};" \
        : "+f"((d)[0]), "+f"((d)[1]), "+f"((d)[2]), "+f"((d)[3]) \
        : "r"((a)[0]), "r"((a)[1]), "r"((a)[2]), "r"((a)[3]), "r"((b)[0]), "r"((b)[1]))

#define CP16(saddr, gptr) \
    asm volatile("cp.async.cg.shared.global [%0], [%1], 16;" :: "r"(saddr), "l"(gptr) : "memory")
#define CP_COMMIT() asm volatile("cp.async.commit_group;" ::: "memory")
#define CP_WAIT2()  asm volatile("cp.async.wait_group 2;" ::: "memory")
#define CP_WAIT1()  asm volatile("cp.async.wait_group 1;" ::: "memory")
#define CP_WAIT0()  asm volatile("cp.async.wait_group 0;" ::: "memory")

// feats stage buffer (24 KB per stage): F 128x128B @0, W 64x128B @16384
#define STG_SZ   24576
#define STG_FH   0
#define STG_WH   16384

// quad smem: persistent F [128 rows x 512B] @0 (64KB),
//            A ring 3 x 8KB @65536 (pair-packed 128B rows, 2 mk),
//            V @90112 (512 f), Q @92160 (256 f)
#define ST4_F    0
#define ST4_A    65536
#define A_STG_SZ 8192
#define OFQ4_V   90112
#define OFQ4_Q   92160
#define QUAD4_SMEM 93184

// ---------------------------------------------------------------------------
// split kernels (fp32 -> fp16)
// ---------------------------------------------------------------------------
__global__ __launch_bounds__(256) void k_xsplit(const float* __restrict__ x)
{
    size_t idx = ((size_t)blockIdx.x * 256 + threadIdx.x) * 4;
    float4 v = *(const float4*)&x[idx];
    *(__half2*)&g_xh[idx]     = __floats2half2_rn(v.x, v.y);
    *(__half2*)&g_xh[idx + 2] = __floats2half2_rn(v.z, v.w);
}

// W [k][n] fp32 -> W^T [n][k] fp16 via smem 32x32 transpose
__global__ __launch_bounds__(256) void k_wsplit(const float* __restrict__ W)
{
    __shared__ float t[32][33];
    const int k0 = blockIdx.x * 32;
    const int n0 = blockIdx.y * 32;
    const int tx = threadIdx.x & 31, ty = threadIdx.x >> 5;
#pragma unroll
    for (int i = 0; i < 4; i++)
        t[ty + i * 8][tx] = W[(size_t)(k0 + ty + i * 8) * DF + n0 + tx];
    __syncthreads();
#pragma unroll
    for (int i = 0; i < 4; i++) {
        int n = n0 + ty + i * 8;
        g_Wh[(size_t)n * D_IN + k0 + tx] = __float2half_rn(t[tx][ty + i * 8]);
    }
}

// ---------------------------------------------------------------------------
// k_feats_mma: feats = relu(x @ W + b), single-pass fp16 warp-MMA.
// ---------------------------------------------------------------------------
__global__ __launch_bounds__(256) void k_feats_mma(const float* __restrict__ bias)
{
    extern __shared__ char sm[];
    const uint32_t smb = smem_u32(sm);
    const int tid = threadIdx.x;
    const int lane = tid & 31;
    const int wid = tid >> 5;
    const int warp_m = wid >> 1;
    const int warp_n = wid & 1;
    const int b0 = blockIdx.x * 128;
    const int n0 = blockIdx.y * 64;

    const __half* fh = g_xh + (size_t)b0 * D_IN;
    const __half* ah = g_Wh + (size_t)n0 * D_IN;

    const int aRow[2] = { warp_m * 32 +  0 + (lane & 7) + ((lane >> 3) & 1) * 8,
                          warp_m * 32 + 16 + (lane & 7) + ((lane >> 3) & 1) * 8 };
    const int aG = (lane >> 4) & 1;
    const int bRow[2] = { warp_n * 32 +  0 + (lane & 7) + ((lane >> 4) & 1) * 8,
                          warp_n * 32 + 16 + (lane & 7) + ((lane >> 4) & 1) * 8 };
    const int bG = (lane >> 3) & 1;
    const int aXor[2] = { aRow[0] & 7, aRow[1] & 7 };
    const int bXor[2] = { bRow[0] & 7, bRow[1] & 7 };

    auto stage = [&](int j) {
        const uint32_t sb = smb + (uint32_t)(j & 1) * STG_SZ;
        const int k0 = j * 64;
#pragma unroll
        for (int it = 0; it < 4; it++) {
            int slot = tid + it * 256;
            int row = slot >> 3, g = slot & 7;
            uint32_t off = (uint32_t)(row * 128 + ((g ^ (row & 7)) << 4));
            CP16(sb + STG_FH + off, fh + (size_t)row * D_IN + k0 + g * 8);
        }
#pragma unroll
        for (int it = 0; it < 2; it++) {
            int slot = tid + it * 256;
            int row = slot >> 3, g = slot & 7;
            uint32_t off = (uint32_t)(row * 128 + ((g ^ (row & 7)) << 4));
            CP16(sb + STG_WH + off, ah + (size_t)row * D_IN + k0 + g * 8);
        }
        CP_COMMIT();
    };

    float acc[2][4][4];
#pragma unroll
    for (int mt = 0; mt < 2; mt++)
#pragma unroll
        for (int nt = 0; nt < 4; nt++)
#pragma unroll
            for (int r = 0; r < 4; r++) acc[mt][nt][r] = 0.f;

    stage(0);
#pragma unroll 1
    for (int ci = 0; ci < 16; ci++) {
        if (ci + 1 < 16) { stage(ci + 1); CP_WAIT1(); } else { CP_WAIT0(); }
        __syncthreads();
        const uint32_t sb = smb + (uint32_t)(ci & 1) * STG_SZ;
#pragma unroll
        for (int ks = 0; ks < 4; ks++) {
            uint32_t fa[2][4], bm[2][4];
#pragma unroll
            for (int mt = 0; mt < 2; mt++) {
                uint32_t ga = (uint32_t)(((ks * 2 + aG) ^ aXor[mt]) << 4);
                LDSM4(fa[mt], sb + STG_FH + aRow[mt] * 128 + ga);
            }
#pragma unroll
            for (int pr = 0; pr < 2; pr++) {
                uint32_t gb = (uint32_t)(((ks * 2 + bG) ^ bXor[pr]) << 4);
                LDSM4(bm[pr], sb + STG_WH + bRow[pr] * 128 + gb);
            }
#pragma unroll
            for (int mt = 0; mt < 2; mt++)
#pragma unroll
                for (int nt = 0; nt < 4; nt++)
                    MMA16816(acc[mt][nt], fa[mt], &bm[nt >> 1][(nt & 1) * 2]);
        }
        __syncthreads();
    }

#pragma unroll
    for (int nt = 0; nt < 4; nt++) {
        int c = n0 + warp_n * 32 + nt * 8 + (lane & 3) * 2;
        float bc0 = bias[c], bc1 = bias[c + 1];
#pragma unroll
        for (int mt = 0; mt < 2; mt++) {
#pragma unroll
            for (int half = 0; half < 2; half++) {
                int row = b0 + warp_m * 32 + mt * 16 + (lane >> 2) + half * 8;
                float v0 = acc[mt][nt][half * 2 + 0] + bc0;
                float v1 = acc[mt][nt][half * 2 + 1] + bc1;
                v0 = v0 > 0.f ? v0 : 0.f;
                v1 = v1 > 0.f ? v1 : 0.f;
                *(__half2*)&g_fh[(size_t)row * DF + c] = __floats2half2_rn(v0, v1);
            }
        }
    }
}

// ---------------------------------------------------------------------------
// Kernel: triangular inverse of L = tril(covs[mk]); writes fp32 g_Ainv AND
// fp16 g_Bh (upper triangle zeroed in both).
// ---------------------------------------------------------------------------
__global__ __launch_bounds__(256) void k_trinv(const float* __restrict__ covs)
{
    const int mk = blockIdx.x;
    const int cg = blockIdx.y;
    const int w = threadIdx.x >> 5;
    const int lane = threadIdx.x & 31;
    const int g = w * 8 + cg;
    const int j0 = g * 4;

    const float* L = covs + (size_t)mk * DF * DF;
    float* Ai = g_Ainv + (size_t)mk * DF * DF;
    __half* Bh = g_Bh + (size_t)mk * DF * DF;

    __shared__ float4 xck[8][DF];
    float4* xc = xck[w];

    for (int i = lane; i < j0; i += 32) {
        *(float4*)&Ai[i * DF + j0] = make_float4(0.f, 0.f, 0.f, 0.f);
        __half2 z2 = __floats2half2_rn(0.f, 0.f);
        *(__half2*)&Bh[i * DF + j0]     = z2;
        *(__half2*)&Bh[i * DF + j0 + 2] = z2;
    }

    for (int i = j0; i < DF; i++) {
        float4 s = make_float4(0.f, 0.f, 0.f, 0.f);
        for (int k = j0 + lane; k < i; k += 32) {
            float lik = L[i * DF + k];
            float4 xv = xc[k];
            s.x = fmaf(lik, xv.x, s.x);
            s.y = fmaf(lik, xv.y, s.y);
            s.z = fmaf(lik, xv.z, s.z);
            s.w = fmaf(lik, xv.w, s.w);
        }
#pragma unroll
        for (int off = 16; off > 0; off >>= 1) {
            s.x += __shfl_xor_sync(0xFFFFFFFFu, s.x, off);
            s.y += __shfl_xor_sync(0xFFFFFFFFu, s.y, off);
            s.z += __shfl_xor_sync(0xFFFFFFFFu, s.z, off);
            s.w += __shfl_xor_sync(0xFFFFFFFFu, s.w, off);
        }
        if (lane == 0) {
            float inv = 1.0f / L[i * DF + i];
            float4 xr;
            xr.x = ((i == j0 + 0 ? 1.0f : 0.0f) - s.x) * inv;
            xr.y = ((i == j0 + 1 ? 1.0f : 0.0f) - s.y) * inv;
            xr.z = ((i == j0 + 2 ? 1.0f : 0.0f) - s.z) * inv;
            xr.w = ((i == j0 + 3 ? 1.0f : 0.0f) - s.w) * inv;
            xc[i] = xr;
            *(float4*)&Ai[i * DF + j0] = xr;
            *(__half2*)&Bh[i * DF + j0]     = __floats2half2_rn(xr.x, xr.y);
            *(__half2*)&Bh[i * DF + j0 + 2] = __floats2half2_rn(xr.z, xr.w);
        }
        __syncwarp();
    }
}

// ---------------------------------------------------------------------------
// Kernel: v[mk][d] = sum_k Ainv[mk][d][k] * mean[mk][k]  (grid (80,4))
// ---------------------------------------------------------------------------
__global__ __launch_bounds__(256) void k_vprep(const float* __restrict__ means)
{
    const int mk = blockIdx.x;
    const int d0 = blockIdx.y * 64;
    const int tid = threadIdx.x;
    const int w = tid >> 5;
    const int lane = tid & 31;
    __shared__ float ms[DF];
    ms[tid] = means[mk * DF + tid];
    __syncthreads();
    const float* Ai = g_Ainv + (size_t)mk * DF * DF;
    for (int d = d0 + w; d < d0 + 64; d += 8) {
        float s = 0.0f;
        for (int k = lane; k < DF; k += 32)
            s = fmaf(Ai[d * DF + k], ms[k], s);
#pragma unroll
        for (int off = 16; off > 0; off >>= 1)
            s += __shfl_xor_sync(0xFFFFFFFFu, s, off);
        if (lane == 0) g_v[mk * DF + d] = s;
    }
}

// ---------------------------------------------------------------------------
// Kernel: per-component constants, one warp per mk (grid 80, block 32)
// ---------------------------------------------------------------------------
__global__ __launch_bounds__(32) void k_prep(const float* __restrict__ covs,
                                             const float* __restrict__ weights)
{
    const int mk = blockIdx.x;
    const int lane = threadIdx.x;
    const float* L = covs + (size_t)mk * DF * DF;
    float logdet = 0.0f;
    for (int i = lane; i < DF; i += 32)
        logdet += logf(L[i * DF + i]);
#pragma unroll
    for (int off = 16; off > 0; off >>= 1)
        logdet += __shfl_xor_sync(0xFFFFFFFFu, logdet, off);
    if (lane == 0) {
        const int m = mk >> 3;
        float wk[NK];
        float mx = -1e30f;
#pragma unroll
        for (int j = 0; j < NK; j++) { wk[j] = weights[m * NK + j]; mx = fmaxf(mx, wk[j]); }
        float sum = 0.f;
#pragma unroll
        for (int j = 0; j < NK; j++) sum += expf(wk[j] - mx);
        float wsm = expf(weights[mk] - mx) / sum;
        g_c1[mk] = -0.5f * wsm;
        g_c2[mk] = wsm * (-0.5f * (float)DF * LOG2PI_F) - wsm * logdet;
    }
}

// ---------------------------------------------------------------------------
// Kernel (hot): fp16 warp-MMA + fused Mahalanobis epilogue.
// F tile (128 rows x 256 k) persistent in smem, staged ONCE.
// A streamed in 20 K=32 chunks (2 mk), 3-stage ring, triangular skip.
// ---------------------------------------------------------------------------
__global__ __launch_bounds__(256, 2) void k_quad_mma(float* __restrict__ out)
{
    extern __shared__ char sm[];
    const uint32_t smb = smem_u32(sm);
    const int tid = threadIdx.x;
    const int lane = tid & 31;
    const int wid = tid >> 5;
    const int warp_m = wid >> 1;      // 0..3
    const int warp_mk = wid & 1;      // 0..1
    const int mk0 = blockIdx.y * 2;
    const int b0 = blockIdx.x * 128;

    ((float*)(sm + OFQ4_V))[tid]       = g_v[mk0 * DF + tid];
    ((float*)(sm + OFQ4_V))[256 + tid] = g_v[(mk0 + 1) * DF + tid];

    const __half* fh = g_fh + (size_t)b0 * DF;
    const __half* ap[2] = { g_Bh + (size_t)mk0 * DF * DF,
                            g_Bh + (size_t)(mk0 + 1) * DF * DF };

    // ---- stage persistent F: 128 rows x 32 groups of 16B, swizzled ----
    // off = r*512 + ((g&24) | ((g&7)^(r&7))) * 16
#pragma unroll
    for (int it = 0; it < 16; it++) {
        int u = tid + it * 256;          // 0..4095
        int r = u >> 5, g = u & 31;
        uint32_t off = (uint32_t)(r * 512 + (((g & 24) | ((g & 7) ^ (r & 7))) << 4));
        CP16(smb + ST4_F + off, fh + (size_t)r * DF + g * 8);
    }
    CP_COMMIT();   // F group: oldest, drains first in wait-group arithmetic

    // F ldmatrix lane addressing: row rA, group g = ck*4 + ks*2 + gsel
    int rA[2];
#pragma unroll
    for (int mt = 0; mt < 2; mt++)
        rA[mt] = warp_m * 32 + mt * 16 + (lane & 7) + ((lane >> 3) & 1) * 8;
    const int gselA = (lane >> 4) & 1;

    // A ldmatrix (pair-packed 128B rows, as before)
    int sB[4], gB[4];
#pragma unroll
    for (int pr = 0; pr < 4; pr++) {
        int r = pr * 16 + (lane & 7) + ((lane >> 4) & 1) * 8;
        sB[pr] = r >> 1;
        gB[pr] = (r & 1) * 4 + ((lane >> 3) & 1);
    }
    const uint32_t abuf = smb + ST4_A + (uint32_t)warp_mk * 4096;

    auto stageA = [&](int j) {
        const uint32_t sb = smb + ST4_A + (uint32_t)(j % 3) * A_STG_SZ;
        const int k0 = c_CK3[j] * 32;
        const int ar0 = c_CD3[j] * 64;
        const bool diag = (k0 == ar0 + 32);
#pragma unroll
        for (int it = 0; it < 2; it++) {
            int u = tid + it * 256;
            int mki = u >> 8;
            int v = u & 255;
            int s = v >> 3, gg = v & 7;
            int r = s * 2 + (gg >> 2);          // local A row 0..63
            if (!(diag && r < 32)) {            // skip all-zero rows in diag chunk
                uint32_t off = (uint32_t)(s * 128 + ((gg ^ (s & 7)) << 4));
                CP16(sb + mki * 4096 + off,
                     ap[mki] + (size_t)(ar0 + r) * DF + k0 + (gg & 3) * 8);
            }
        }
        CP_COMMIT();
    };

    float qrow[4] = {0.f, 0.f, 0.f, 0.f};
    const float* vptr = (const float*)(sm + OFQ4_V) + warp_mk * DF;

    stageA(0);
    stageA(1);
    int ci = 0;
#pragma unroll 1
    for (int dblk = 0; dblk < 4; dblk++) {
        const int nrow0 = dblk * 64;
        const int nch = 2 * (dblk + 1);
        float acc[2][8][4];
#pragma unroll
        for (int mt = 0; mt < 2; mt++)
#pragma unroll
            for (int nt = 0; nt < 8; nt++)
#pragma unroll
                for (int r = 0; r < 4; r++) acc[mt][nt][r] = 0.f;

#pragma unroll 1
        for (int kc = 0; kc < nch; kc++) {
            if (ci + 2 < 20) stageA(ci + 2);
            {
                int pending = 19 - ci;
                if (pending >= 2) CP_WAIT2();
                else if (pending == 1) CP_WAIT1();
                else CP_WAIT0();
            }
            __syncthreads();
            const uint32_t sbA = smb + ST4_A + (uint32_t)(ci % 3) * A_STG_SZ;
            const int ck = c_CK3[ci];
            const int prStart = (kc == nch - 1) ? 2 : 0;  // diag: rows<32 zero
#pragma unroll
            for (int ks = 0; ks < 2; ks++) {
                uint32_t fa[2][4];
#pragma unroll
                for (int mt = 0; mt < 2; mt++) {
                    int g = ck * 4 + ks * 2 + gselA;
                    uint32_t off = (uint32_t)(rA[mt] * 512 +
                        (((g & 24) | ((g & 7) ^ (rA[mt] & 7))) << 4));
                    LDSM4(fa[mt], smb + ST4_F + off);
                }
#pragma unroll
                for (int pr = 0; pr < 4; pr++) {
                    if (pr >= prStart) {
                        uint32_t bm[4];
                        uint32_t offb = (uint32_t)(sB[pr] * 128 +
                            (((gB[pr] + ks * 2) ^ (sB[pr] & 7)) << 4));
                        LDSM4(bm, sbA + (uint32_t)warp_mk * 4096 + offb);
#pragma unroll
                        for (int mt = 0; mt < 2; mt++)
#pragma unroll
                            for (int j2 = 0; j2 < 2; j2++)
                                MMA16816(acc[mt][pr * 2 + j2], fa[mt], &bm[j2 * 2]);
                    }
                }
            }
            __syncthreads();
            ci++;
        }

        // fold: z = D - v[d]; qrow += z^2
#pragma unroll
        for (int mt = 0; mt < 2; mt++)
#pragma unroll
            for (int nt = 0; nt < 8; nt++) {
#pragma unroll
                for (int r = 0; r < 4; r++) {
                    int d = nrow0 + nt * 8 + (lane & 3) * 2 + (r & 1);
                    float z = acc[mt][nt][r] - vptr[d];
                    qrow[mt * 2 + (r >> 1)] = fmaf(z, z, qrow[mt * 2 + (r >> 1)]);
                }
            }
    }

    float* qs = (float*)(sm + OFQ4_Q);
#pragma unroll
    for (int i = 0; i < 4; i++) {
        float q = qrow[i];
        q += __shfl_xor_sync(0xFFFFFFFFu, q, 1);
        q += __shfl_xor_sync(0xFFFFFFFFu, q, 2);
        if ((lane & 3) == 0)
            qs[warp_mk * 128 + warp_m * 32 + (i >> 1) * 16 + (i & 1) * 8 + (lane >> 2)] = q;
    }
    __syncthreads();
    {
        int mkloc = tid >> 7;
        int row = tid & 127;
        int mk = mk0 + mkloc;
        out[(size_t)(b0 + row) * NMK + mk] =
            fmaf(g_c1[mk], qs[mkloc * 128 + row], g_c2[mk]);
    }
}

// ---------------------------------------------------------------------------
extern "C" void kernel_launch(void* const* d_in, const int* in_sizes, int n_in,
                              void* d_out, int out_size)
{
    const float* x       = (const float*)d_in[0];
    const float* W       = (const float*)d_in[1];
    const float* bias    = (const float*)d_in[2];
    const float* means   = (const float*)d_in[3];
    const float* covs    = (const float*)d_in[4];
    const float* weights = (const float*)d_in[5];
    float* out = (float*)d_out;

    cudaFuncSetAttribute(k_quad_mma, cudaFuncAttributeMaxDynamicSharedMemorySize,
                         QUAD4_SMEM);
    cudaFuncSetAttribute(k_feats_mma, cudaFuncAttributeMaxDynamicSharedMemorySize,
                         2 * STG_SZ);

    k_xsplit<<<(BATCH * D_IN) / 1024, 256>>>(x);
    k_wsplit<<<dim3(D_IN / 32, DF / 32), 256>>>(W);
    k_trinv<<<dim3(NMK, 8), 256>>>(covs);
    k_feats_mma<<<dim3(BATCH / 128, DF / 64), 256, 2 * STG_SZ>>>(bias);
    k_vprep<<<dim3(NMK, 4), 256>>>(means);
    k_prep<<<NMK, 32>>>(covs, weights);
    k_quad_mma<<<dim3(BATCH / 128, NMK / 2), 256, QUAD4_SMEM>>>(out);
}

// round 13
// speedup vs baseline: 1.4881x; 1.0187x over previous
#include <cuda_runtime.h>
#include <cuda_fp16.h>
#include <cstdint>
#include <math.h>

// Problem constants
#define BATCH 4096
#define D_IN  1024
#define DF    256
#define NM    10
#define NK    8
#define NMK   80
#define LOG2PI_F 1.8378770664093453f

// ---------------- scratch (no cudaMalloc allowed) ----------------
__device__ __align__(16) float  g_Ainv[NMK * DF * DF]; // fp32 L^-1 (upper zeroed)
__device__ __align__(16) __half g_xh[BATCH * D_IN];    // x fp16, [b][k]
__device__ __align__(16) __half g_Wh[DF * D_IN];       // W^T fp16, [n][k]
__device__ __align__(16) __half g_fh[BATCH * DF];      // feats fp16, [b][d]
__device__ __align__(16) __half g_Bh[NMK * DF * DF];   // Ainv fp16, [mk][d][k]
__device__ float g_v[NMK * DF];                         // Ainv @ mean (fp32)
__device__ float g_c1[NMK];                             // -0.5 * w
__device__ float g_c2[NMK];                             // w*(-0.5*DF*log2pi) - w*logdet

// quad chunk schedule: 10 K=64 chunks, dblk-major
__constant__ int c_CD4[10] = {0, 1,1, 2,2,2, 3,3,3,3};
__constant__ int c_CK4[10] = {0, 0,1, 0,1,2, 0,1,2,3};

// ---------------- helpers ----------------
__device__ __forceinline__ uint32_t smem_u32(const void* p) {
    uint32_t a;
    asm("{ .reg .u64 t; cvta.to.shared.u64 t, %1; cvt.u32.u64 %0, t; }" : "=r"(a) : "l"(p));
    return a;
}

#define LDSM4(r, addr) \
    asm volatile("ldmatrix.sync.aligned.m8n8.x4.shared.b16 {%0,%1,%2,%3}, [%4];" \
        : "=r"((r)[0]), "=r"((r)[1]), "=r"((r)[2]), "=r"((r)[3]) : "r"(addr))

#define MMA16816(d, a, b) \
    asm volatile("mma.sync.aligned.m16n8k16.row.col.f32.f16.f16.f32 " \
        "{%0,%1,%2,%3},{%4,%5,%6,%7},{%8,%9},{%0,%1,%2,%3};" \
        : "+f"((d)[0]), "+f"((d)[1]), "+f"((d)[2]), "+f"((d)[3]) \
        : "r"((a)[0]), "r"((a)[1]), "r"((a)[2]), "r"((a)[3]), "r"((b)[0]), "r"((b)[1]))

#define CP16(saddr, gptr) \
    asm volatile("cp.async.cg.shared.global [%0], [%1], 16;" :: "r"(saddr), "l"(gptr) : "memory")
#define CP_COMMIT() asm volatile("cp.async.commit_group;" ::: "memory")
#define CP_WAIT1()  asm volatile("cp.async.wait_group 1;" ::: "memory")
#define CP_WAIT0()  asm volatile("cp.async.wait_group 0;" ::: "memory")

// feats stage buffer (24 KB per stage): F 128x128B @0, W 64x128B @16384
#define STG_SZ   24576
#define STG_FH   0
#define STG_WH   16384

// quad smem: persistent F [128 rows x 512B] @0 (64KB),
//            A ring 2 x 16KB @65536 (per stage: 2 mk x 64 rows x 128B),
//            V @98304 (512 f), Q @100352 (256 f)
#define ST4_F    0
#define ST4_A    65536
#define A_STG_SZ 16384
#define OFQ4_V   98304
#define OFQ4_Q   100352
#define QUAD4_SMEM 101376

// ---------------------------------------------------------------------------
// split kernels (fp32 -> fp16)
// ---------------------------------------------------------------------------
__global__ __launch_bounds__(256) void k_xsplit(const float* __restrict__ x)
{
    size_t idx = ((size_t)blockIdx.x * 256 + threadIdx.x) * 4;
    float4 v = *(const float4*)&x[idx];
    *(__half2*)&g_xh[idx]     = __floats2half2_rn(v.x, v.y);
    *(__half2*)&g_xh[idx + 2] = __floats2half2_rn(v.z, v.w);
}

// W [k][n] fp32 -> W^T [n][k] fp16 via smem 32x32 transpose
__global__ __launch_bounds__(256) void k_wsplit(const float* __restrict__ W)
{
    __shared__ float t[32][33];
    const int k0 = blockIdx.x * 32;
    const int n0 = blockIdx.y * 32;
    const int tx = threadIdx.x & 31, ty = threadIdx.x >> 5;
#pragma unroll
    for (int i = 0; i < 4; i++)
        t[ty + i * 8][tx] = W[(size_t)(k0 + ty + i * 8) * DF + n0 + tx];
    __syncthreads();
#pragma unroll
    for (int i = 0; i < 4; i++) {
        int n = n0 + ty + i * 8;
        g_Wh[(size_t)n * D_IN + k0 + tx] = __float2half_rn(t[tx][ty + i * 8]);
    }
}

// ---------------------------------------------------------------------------
// k_feats_mma: feats = relu(x @ W + b), single-pass fp16 warp-MMA. (unchanged)
// ---------------------------------------------------------------------------
__global__ __launch_bounds__(256) void k_feats_mma(const float* __restrict__ bias)
{
    extern __shared__ char sm[];
    const uint32_t smb = smem_u32(sm);
    const int tid = threadIdx.x;
    const int lane = tid & 31;
    const int wid = tid >> 5;
    const int warp_m = wid >> 1;
    const int warp_n = wid & 1;
    const int b0 = blockIdx.x * 128;
    const int n0 = blockIdx.y * 64;

    const __half* fh = g_xh + (size_t)b0 * D_IN;
    const __half* ah = g_Wh + (size_t)n0 * D_IN;

    const int aRow[2] = { warp_m * 32 +  0 + (lane & 7) + ((lane >> 3) & 1) * 8,
                          warp_m * 32 + 16 + (lane & 7) + ((lane >> 3) & 1) * 8 };
    const int aG = (lane >> 4) & 1;
    const int bRow[2] = { warp_n * 32 +  0 + (lane & 7) + ((lane >> 4) & 1) * 8,
                          warp_n * 32 + 16 + (lane & 7) + ((lane >> 4) & 1) * 8 };
    const int bG = (lane >> 3) & 1;
    const int aXor[2] = { aRow[0] & 7, aRow[1] & 7 };
    const int bXor[2] = { bRow[0] & 7, bRow[1] & 7 };

    auto stage = [&](int j) {
        const uint32_t sb = smb + (uint32_t)(j & 1) * STG_SZ;
        const int k0 = j * 64;
#pragma unroll
        for (int it = 0; it < 4; it++) {
            int slot = tid + it * 256;
            int row = slot >> 3, g = slot & 7;
            uint32_t off = (uint32_t)(row * 128 + ((g ^ (row & 7)) << 4));
            CP16(sb + STG_FH + off, fh + (size_t)row * D_IN + k0 + g * 8);
        }
#pragma unroll
        for (int it = 0; it < 2; it++) {
            int slot = tid + it * 256;
            int row = slot >> 3, g = slot & 7;
            uint32_t off = (uint32_t)(row * 128 + ((g ^ (row & 7)) << 4));
            CP16(sb + STG_WH + off, ah + (size_t)row * D_IN + k0 + g * 8);
        }
        CP_COMMIT();
    };

    float acc[2][4][4];
#pragma unroll
    for (int mt = 0; mt < 2; mt++)
#pragma unroll
        for (int nt = 0; nt < 4; nt++)
#pragma unroll
            for (int r = 0; r < 4; r++) acc[mt][nt][r] = 0.f;

    stage(0);
#pragma unroll 1
    for (int ci = 0; ci < 16; ci++) {
        if (ci + 1 < 16) { stage(ci + 1); CP_WAIT1(); } else { CP_WAIT0(); }
        __syncthreads();
        const uint32_t sb = smb + (uint32_t)(ci & 1) * STG_SZ;
#pragma unroll
        for (int ks = 0; ks < 4; ks++) {
            uint32_t fa[2][4], bm[2][4];
#pragma unroll
            for (int mt = 0; mt < 2; mt++) {
                uint32_t ga = (uint32_t)(((ks * 2 + aG) ^ aXor[mt]) << 4);
                LDSM4(fa[mt], sb + STG_FH + aRow[mt] * 128 + ga);
            }
#pragma unroll
            for (int pr = 0; pr < 2; pr++) {
                uint32_t gb = (uint32_t)(((ks * 2 + bG) ^ bXor[pr]) << 4);
                LDSM4(bm[pr], sb + STG_WH + bRow[pr] * 128 + gb);
            }
#pragma unroll
            for (int mt = 0; mt < 2; mt++)
#pragma unroll
                for (int nt = 0; nt < 4; nt++)
                    MMA16816(acc[mt][nt], fa[mt], &bm[nt >> 1][(nt & 1) * 2]);
        }
        __syncthreads();
    }

#pragma unroll
    for (int nt = 0; nt < 4; nt++) {
        int c = n0 + warp_n * 32 + nt * 8 + (lane & 3) * 2;
        float bc0 = bias[c], bc1 = bias[c + 1];
#pragma unroll
        for (int mt = 0; mt < 2; mt++) {
#pragma unroll
            for (int half = 0; half < 2; half++) {
                int row = b0 + warp_m * 32 + mt * 16 + (lane >> 2) + half * 8;
                float v0 = acc[mt][nt][half * 2 + 0] + bc0;
                float v1 = acc[mt][nt][half * 2 + 1] + bc1;
                v0 = v0 > 0.f ? v0 : 0.f;
                v1 = v1 > 0.f ? v1 : 0.f;
                *(__half2*)&g_fh[(size_t)row * DF + c] = __floats2half2_rn(v0, v1);
            }
        }
    }
}

// ---------------------------------------------------------------------------
// Kernel: triangular inverse of L; writes fp32 g_Ainv AND fp16 g_Bh.
// ---------------------------------------------------------------------------
__global__ __launch_bounds__(256) void k_trinv(const float* __restrict__ covs)
{
    const int mk = blockIdx.x;
    const int cg = blockIdx.y;
    const int w = threadIdx.x >> 5;
    const int lane = threadIdx.x & 31;
    const int g = w * 8 + cg;
    const int j0 = g * 4;

    const float* L = covs + (size_t)mk * DF * DF;
    float* Ai = g_Ainv + (size_t)mk * DF * DF;
    __half* Bh = g_Bh + (size_t)mk * DF * DF;

    __shared__ float4 xck[8][DF];
    float4* xc = xck[w];

    for (int i = lane; i < j0; i += 32) {
        *(float4*)&Ai[i * DF + j0] = make_float4(0.f, 0.f, 0.f, 0.f);
        __half2 z2 = __floats2half2_rn(0.f, 0.f);
        *(__half2*)&Bh[i * DF + j0]     = z2;
        *(__half2*)&Bh[i * DF + j0 + 2] = z2;
    }

    for (int i = j0; i < DF; i++) {
        float4 s = make_float4(0.f, 0.f, 0.f, 0.f);
        for (int k = j0 + lane; k < i; k += 32) {
            float lik = L[i * DF + k];
            float4 xv = xc[k];
            s.x = fmaf(lik, xv.x, s.x);
            s.y = fmaf(lik, xv.y, s.y);
            s.z = fmaf(lik, xv.z, s.z);
            s.w = fmaf(lik, xv.w, s.w);
        }
#pragma unroll
        for (int off = 16; off > 0; off >>= 1) {
            s.x += __shfl_xor_sync(0xFFFFFFFFu, s.x, off);
            s.y += __shfl_xor_sync(0xFFFFFFFFu, s.y, off);
            s.z += __shfl_xor_sync(0xFFFFFFFFu, s.z, off);
            s.w += __shfl_xor_sync(0xFFFFFFFFu, s.w, off);
        }
        if (lane == 0) {
            float inv = 1.0f / L[i * DF + i];
            float4 xr;
            xr.x = ((i == j0 + 0 ? 1.0f : 0.0f) - s.x) * inv;
            xr.y = ((i == j0 + 1 ? 1.0f : 0.0f) - s.y) * inv;
            xr.z = ((i == j0 + 2 ? 1.0f : 0.0f) - s.z) * inv;
            xr.w = ((i == j0 + 3 ? 1.0f : 0.0f) - s.w) * inv;
            xc[i] = xr;
            *(float4*)&Ai[i * DF + j0] = xr;
            *(__half2*)&Bh[i * DF + j0]     = __floats2half2_rn(xr.x, xr.y);
            *(__half2*)&Bh[i * DF + j0 + 2] = __floats2half2_rn(xr.z, xr.w);
        }
        __syncwarp();
    }
}

// ---------------------------------------------------------------------------
// Kernel: v[mk][d] = sum_k Ainv[mk][d][k] * mean[mk][k]  (grid (80,4))
// ---------------------------------------------------------------------------
__global__ __launch_bounds__(256) void k_vprep(const float* __restrict__ means)
{
    const int mk = blockIdx.x;
    const int d0 = blockIdx.y * 64;
    const int tid = threadIdx.x;
    const int w = tid >> 5;
    const int lane = tid & 31;
    __shared__ float ms[DF];
    ms[tid] = means[mk * DF + tid];
    __syncthreads();
    const float* Ai = g_Ainv + (size_t)mk * DF * DF;
    for (int d = d0 + w; d < d0 + 64; d += 8) {
        float s = 0.0f;
        for (int k = lane; k < DF; k += 32)
            s = fmaf(Ai[d * DF + k], ms[k], s);
#pragma unroll
        for (int off = 16; off > 0; off >>= 1)
            s += __shfl_xor_sync(0xFFFFFFFFu, s, off);
        if (lane == 0) g_v[mk * DF + d] = s;
    }
}

// ---------------------------------------------------------------------------
// Kernel: per-component constants, one warp per mk (grid 80, block 32)
// ---------------------------------------------------------------------------
__global__ __launch_bounds__(32) void k_prep(const float* __restrict__ covs,
                                             const float* __restrict__ weights)
{
    const int mk = blockIdx.x;
    const int lane = threadIdx.x;
    const float* L = covs + (size_t)mk * DF * DF;
    float logdet = 0.0f;
    for (int i = lane; i < DF; i += 32)
        logdet += logf(L[i * DF + i]);
#pragma unroll
    for (int off = 16; off > 0; off >>= 1)
        logdet += __shfl_xor_sync(0xFFFFFFFFu, logdet, off);
    if (lane == 0) {
        const int m = mk >> 3;
        float wk[NK];
        float mx = -1e30f;
#pragma unroll
        for (int j = 0; j < NK; j++) { wk[j] = weights[m * NK + j]; mx = fmaxf(mx, wk[j]); }
        float sum = 0.f;
#pragma unroll
        for (int j = 0; j < NK; j++) sum += expf(wk[j] - mx);
        float wsm = expf(weights[mk] - mx) / sum;
        g_c1[mk] = -0.5f * wsm;
        g_c2[mk] = wsm * (-0.5f * (float)DF * LOG2PI_F) - wsm * logdet;
    }
}

// ---------------------------------------------------------------------------
// Kernel (hot): fp16 warp-MMA + fused Mahalanobis epilogue.
// F tile persistent (staged once). A streamed in 10 K=64 chunks (2 mk),
// 2-stage ring, triangular MMA skip (pr>=ks in diag chunks) + staging skip.
// ---------------------------------------------------------------------------
__global__ __launch_bounds__(256, 2) void k_quad_mma(float* __restrict__ out)
{
    extern __shared__ char sm[];
    const uint32_t smb = smem_u32(sm);
    const int tid = threadIdx.x;
    const int lane = tid & 31;
    const int wid = tid >> 5;
    const int warp_m = wid >> 1;      // 0..3
    const int warp_mk = wid & 1;      // 0..1
    const int mk0 = blockIdx.y * 2;
    const int b0 = blockIdx.x * 128;

    ((float*)(sm + OFQ4_V))[tid]       = g_v[mk0 * DF + tid];
    ((float*)(sm + OFQ4_V))[256 + tid] = g_v[(mk0 + 1) * DF + tid];

    const __half* fh = g_fh + (size_t)b0 * DF;
    const __half* ap[2] = { g_Bh + (size_t)mk0 * DF * DF,
                            g_Bh + (size_t)(mk0 + 1) * DF * DF };

    // ---- stage persistent F: 128 rows x 32 groups of 16B, swizzled ----
#pragma unroll
    for (int it = 0; it < 16; it++) {
        int u = tid + it * 256;          // 0..4095
        int r = u >> 5, g = u & 31;
        uint32_t off = (uint32_t)(r * 512 + (((g & 24) | ((g & 7) ^ (r & 7))) << 4));
        CP16(smb + ST4_F + off, fh + (size_t)r * DF + g * 8);
    }
    CP_COMMIT();   // F group drains with the first A-chunk wait

    // F ldmatrix lane addressing
    int rA[2];
#pragma unroll
    for (int mt = 0; mt < 2; mt++)
        rA[mt] = warp_m * 32 + mt * 16 + (lane & 7) + ((lane >> 3) & 1) * 8;
    const int gselA = (lane >> 4) & 1;

    // A ldmatrix lane addressing (64 rows x 128B, classic swizzle)
    int rB[4];
#pragma unroll
    for (int pr = 0; pr < 4; pr++)
        rB[pr] = pr * 16 + (lane & 7) + ((lane >> 4) & 1) * 8;
    const int gselB = (lane >> 3) & 1;

    auto stageA = [&](int j) {
        const uint32_t sb = smb + ST4_A + (uint32_t)(j & 1) * A_STG_SZ;
        const int k0 = c_CK4[j] * 64;
        const int ar0 = c_CD4[j] * 64;
        const bool diag = (c_CK4[j] == c_CD4[j]);
#pragma unroll
        for (int it = 0; it < 4; it++) {
            int u = tid + it * 256;             // 0..1023
            int mki = u >> 9;
            int v = u & 511;
            int r = v >> 3, g = v & 7;          // A row 0..63, 16B group 0..7
            // diag chunk: stage only 16x16 tiles on/below diagonal
            if (!diag || ((g >> 1) <= (r >> 4))) {
                uint32_t off = (uint32_t)(r * 128 + ((g ^ (r & 7)) << 4));
                CP16(sb + mki * 8192 + off,
                     ap[mki] + (size_t)(ar0 + r) * DF + k0 + g * 8);
            }
        }
        CP_COMMIT();
    };

    float qrow[4] = {0.f, 0.f, 0.f, 0.f};
    const float* vptr = (const float*)(sm + OFQ4_V) + warp_mk * DF;

    stageA(0);
    int ci = 0;
#pragma unroll 1
    for (int dblk = 0; dblk < 4; dblk++) {
        const int nrow0 = dblk * 64;
        const int nch = dblk + 1;
        float acc[2][8][4];
#pragma unroll
        for (int mt = 0; mt < 2; mt++)
#pragma unroll
            for (int nt = 0; nt < 8; nt++)
#pragma unroll
                for (int r = 0; r < 4; r++) acc[mt][nt][r] = 0.f;

#pragma unroll 1
        for (int kc = 0; kc < nch; kc++) {
            if (ci + 1 < 10) { stageA(ci + 1); CP_WAIT1(); } else { CP_WAIT0(); }
            __syncthreads();
            const uint32_t sbA = smb + ST4_A + (uint32_t)(ci & 1) * A_STG_SZ
                               + (uint32_t)warp_mk * 8192;
            const int ck = c_CK4[ci];
            const bool diag = (kc == nch - 1);   // kc == dblk
#pragma unroll
            for (int ks = 0; ks < 4; ks++) {
                uint32_t fa[2][4];
#pragma unroll
                for (int mt = 0; mt < 2; mt++) {
                    int g = ck * 8 + ks * 2 + gselA;
                    uint32_t off = (uint32_t)(rA[mt] * 512 +
                        (((g & 24) | ((g & 7) ^ (rA[mt] & 7))) << 4));
                    LDSM4(fa[mt], smb + ST4_F + off);
                }
#pragma unroll
                for (int pr = 0; pr < 4; pr++) {
                    if (!diag || pr >= ks) {
                        uint32_t bm[4];
                        uint32_t offb = (uint32_t)(rB[pr] * 128 +
                            (((ks * 2 + gselB) ^ (rB[pr] & 7)) << 4));
                        LDSM4(bm, sbA + offb);
#pragma unroll
                        for (int mt = 0; mt < 2; mt++)
#pragma unroll
                            for (int j2 = 0; j2 < 2; j2++)
                                MMA16816(acc[mt][pr * 2 + j2], fa[mt], &bm[j2 * 2]);
                    }
                }
            }
            __syncthreads();
            ci++;
        }

        // fold: z = D - v[d]; qrow += z^2
#pragma unroll
        for (int mt = 0; mt < 2; mt++)
#pragma unroll
            for (int nt = 0; nt < 8; nt++) {
#pragma unroll
                for (int r = 0; r < 4; r++) {
                    int d = nrow0 + nt * 8 + (lane & 3) * 2 + (r & 1);
                    float z = acc[mt][nt][r] - vptr[d];
                    qrow[mt * 2 + (r >> 1)] = fmaf(z, z, qrow[mt * 2 + (r >> 1)]);
                }
            }
    }

    float* qs = (float*)(sm + OFQ4_Q);
#pragma unroll
    for (int i = 0; i < 4; i++) {
        float q = qrow[i];
        q += __shfl_xor_sync(0xFFFFFFFFu, q, 1);
        q += __shfl_xor_sync(0xFFFFFFFFu, q, 2);
        if ((lane & 3) == 0)
            qs[warp_mk * 128 + warp_m * 32 + (i >> 1) * 16 + (i & 1) * 8 + (lane >> 2)] = q;
    }
    __syncthreads();
    {
        int mkloc = tid >> 7;
        int row = tid & 127;
        int mk = mk0 + mkloc;
        out[(size_t)(b0 + row) * NMK + mk] =
            fmaf(g_c1[mk], qs[mkloc * 128 + row], g_c2[mk]);
    }
}

// ---------------------------------------------------------------------------
extern "C" void kernel_launch(void* const* d_in, const int* in_sizes, int n_in,
                              void* d_out, int out_size)
{
    const float* x       = (const float*)d_in[0];
    const float* W       = (const float*)d_in[1];
    const float* bias    = (const float*)d_in[2];
    const float* means   = (const float*)d_in[3];
    const float* covs    = (const float*)d_in[4];
    const float* weights = (const float*)d_in[5];
    float* out = (float*)d_out;

    cudaFuncSetAttribute(k_quad_mma, cudaFuncAttributeMaxDynamicSharedMemorySize,
                         QUAD4_SMEM);
    cudaFuncSetAttribute(k_feats_mma, cudaFuncAttributeMaxDynamicSharedMemorySize,
                         2 * STG_SZ);

    k_xsplit<<<(BATCH * D_IN) / 1024, 256>>>(x);
    k_wsplit<<<dim3(D_IN / 32, DF / 32), 256>>>(W);
    k_trinv<<<dim3(NMK, 8), 256>>>(covs);
    k_feats_mma<<<dim3(BATCH / 128, DF / 64), 256, 2 * STG_SZ>>>(bias);
    k_vprep<<<dim3(NMK, 4), 256>>>(means);
    k_prep<<<NMK, 32>>>(covs, weights);
    k_quad_mma<<<dim3(BATCH / 128, NMK / 2), 256, QUAD4_SMEM>>>(out);
}